// round 2
// baseline (speedup 1.0000x reference)
#include <cuda_runtime.h>
#include <math.h>

// ---------------- problem constants ----------------
#define BB   64      // batch
#define TT   1024    // time steps
#define II   64      // input dim
#define HH   512     // hidden dim
#define LL   128     // latent dim

// ---------------- launch geometry ----------------
#define NCTA 128     // <= #SMs (148) -> all CTAs co-resident -> grid barrier safe
#define NTHR 128
#define UPC  16      // units per CTA   (32 unit-groups)
#define BPC  16      // batches per CTA (4 batch-groups)

// ---------------- shared memory layout (floats) ----------------
// row strides chosen so stride mod 32 == 2 -> 16 unit rows hit distinct bank pairs
#define RSH 514      // 512-wide rows (weights vs H, h-state, out_W)
#define RSX 66       // 64-wide rows (x tile, W_ih slice)
#define RSZ 130      // 128-wide rows (z tile)
#define RSO 514

#define OFF_WSH 0
#define SZ_WSH  (3*UPC*RSH)              /* 24672 */
#define OFF_WSX (OFF_WSH + SZ_WSH)
#define SZ_WSX  (3*UPC*RSX)              /* 3168 */
#define OFF_HS  (OFF_WSX + SZ_WSX)
#define SZ_HS   (BPC*RSH)                /* 8224 */
#define OFF_XS  (OFF_HS + SZ_HS)
#define SZ_XS   (BPC*RSX)                /* 1056 */
#define OFF_ZS  (OFF_XS + SZ_XS)
#define SZ_ZS   (BPC*RSZ)                /* 2080 */
#define OFF_OW  (OFF_ZS + SZ_ZS)
#define SZ_OW   (2*RSO)                  /* 1028 */
#define OFF_BXS (OFF_OW + SZ_OW)         /* 48 */
#define OFF_BHS (OFF_BXS + 48)           /* 48 */
#define OFF_OB  (OFF_BHS + 48)           /* 2 (+pad) */
#define OFF_RED (OFF_OB + 8)             /* 128 */
#define SMEM_FLOATS (OFF_RED + NTHR)
#define SMEM_BYTES  (SMEM_FLOATS * 4)    /* ~162 KB -> 1 CTA/SM */

typedef unsigned long long ull;

// ---------------- device scratch (static; no allocations allowed) ----------------
__device__ float g_h[2][BB][HH];     // hidden-state double buffer
__device__ float g_inp[BB][II];      // decoder feedback input
__device__ float g_z[BB][LL];        // latent sample
__device__ unsigned          g_cnt = 0;
__device__ volatile unsigned g_gen = 0;

// ---------------- packed fp32x2 FMA ----------------
__device__ __forceinline__ void ffma2(ull& d, ull a, ull b) {
    asm("fma.rn.f32x2 %0, %1, %2, %0;" : "+l"(d) : "l"(a), "l"(b));
}
__device__ __forceinline__ float sum2(ull v) {
    return __uint_as_float((unsigned)v) + __uint_as_float((unsigned)(v >> 32));
}
__device__ __forceinline__ float sigm(float x) { return 1.0f / (1.0f + expf(-x)); }

// ---------------- grid barrier (all NCTA CTAs co-resident) ----------------
__device__ __forceinline__ void grid_barrier() {
    __syncthreads();
    if (threadIdx.x == 0) {
        __threadfence();
        unsigned g = g_gen;
        if (atomicAdd(&g_cnt, 1u) == NCTA - 1) {
            g_cnt = 0;
            __threadfence();
            g_gen = g + 1;
        } else {
            while (g_gen == g) { }
        }
        __threadfence();
    }
    __syncthreads();
}

// ---------------- SMEM staging helpers ----------------
__device__ void load_gate_weights(float* sm, const float* W_hh, const float* W_ih,
                                  const float* b_ih, const float* b_hh, int ug) {
    float* wsh = sm + OFF_WSH;
    float* wsx = sm + OFF_WSX;
    for (int idx = threadIdx.x; idx < 48 * HH; idx += NTHR) {
        int r = idx >> 9, k = idx & 511;
        int g = r >> 4, u = r & 15;
        wsh[(g * UPC + u) * RSH + k] = W_hh[(g * HH + ug * UPC + u) * HH + k];
    }
    for (int idx = threadIdx.x; idx < 48 * II; idx += NTHR) {
        int r = idx >> 6, k = idx & 63;
        int g = r >> 4, u = r & 15;
        wsx[(g * UPC + u) * RSX + k] = W_ih[(g * HH + ug * UPC + u) * II + k];
    }
    if (threadIdx.x < 48) {
        int g = threadIdx.x >> 4, u = threadIdx.x & 15;
        sm[OFF_BXS + threadIdx.x] = b_ih[g * HH + ug * UPC + u];
        sm[OFF_BHS + threadIdx.x] = b_hh[g * HH + ug * UPC + u];
    }
}

__device__ void load_hs(float* sm, const float* hsrc, int bg) {
    float* hsm = sm + OFF_HS;
    for (int idx = threadIdx.x; idx < BPC * (HH / 4); idx += NTHR) {
        int b = idx >> 7, q = idx & 127;
        float4 v = reinterpret_cast<const float4*>(hsrc + (bg * BPC + b) * HH)[q];
        float* d = hsm + b * RSH + 4 * q;
        d[0] = v.x; d[1] = v.y; d[2] = v.z; d[3] = v.w;
    }
}

__device__ void load_xs(float* sm, const float* src, int rowstride, int bg) {
    float* xsm = sm + OFF_XS;
    for (int idx = threadIdx.x; idx < BPC * (II / 4); idx += NTHR) {
        int b = idx >> 4, q = idx & 15;
        float4 v = reinterpret_cast<const float4*>(src + (bg * BPC + b) * rowstride)[q];
        float* d = xsm + b * RSX + 4 * q;
        d[0] = v.x; d[1] = v.y; d[2] = v.z; d[3] = v.w;
    }
}

// ---------------- GRU step core ----------------
__device__ void gru_compute_store(float* sm, float* hout, int bg, int ug) {
    const int u  = threadIdx.x & 15;
    const int bp = threadIdx.x >> 4;
    const int b0 = 2 * bp, b1 = b0 + 1;

    const ull* wr = (const ull*)(sm + OFF_WSH + (0 * UPC + u) * RSH);
    const ull* wz = (const ull*)(sm + OFF_WSH + (1 * UPC + u) * RSH);
    const ull* wn = (const ull*)(sm + OFF_WSH + (2 * UPC + u) * RSH);
    const ull* h0 = (const ull*)(sm + OFF_HS + b0 * RSH);
    const ull* h1 = (const ull*)(sm + OFF_HS + b1 * RSH);

    ull ar0 = 0, az0 = 0, anh0 = 0, anx0 = 0;
    ull ar1 = 0, az1 = 0, anh1 = 0, anx1 = 0;

#pragma unroll 4
    for (int p = 0; p < HH / 2; p++) {
        ull a = wr[p], c = wz[p], e = wn[p];
        ull x0 = h0[p], x1 = h1[p];
        ffma2(ar0, x0, a);  ffma2(ar1, x1, a);
        ffma2(az0, x0, c);  ffma2(az1, x1, c);
        ffma2(anh0, x0, e); ffma2(anh1, x1, e);
    }

    const ull* xr = (const ull*)(sm + OFF_WSX + (0 * UPC + u) * RSX);
    const ull* xz = (const ull*)(sm + OFF_WSX + (1 * UPC + u) * RSX);
    const ull* xn = (const ull*)(sm + OFF_WSX + (2 * UPC + u) * RSX);
    const ull* q0 = (const ull*)(sm + OFF_XS + b0 * RSX);
    const ull* q1 = (const ull*)(sm + OFF_XS + b1 * RSX);

#pragma unroll 4
    for (int p = 0; p < II / 2; p++) {
        ull a = xr[p], c = xz[p], e = xn[p];
        ull x0 = q0[p], x1 = q1[p];
        ffma2(ar0, x0, a);  ffma2(ar1, x1, a);
        ffma2(az0, x0, c);  ffma2(az1, x1, c);
        ffma2(anx0, x0, e); ffma2(anx1, x1, e);
    }

    const float br  = sm[OFF_BXS + u]      + sm[OFF_BHS + u];
    const float bz  = sm[OFF_BXS + 16 + u] + sm[OFF_BHS + 16 + u];
    const float bxn = sm[OFF_BXS + 32 + u];
    const float bhn = sm[OFF_BHS + 32 + u];
    const int U = ug * UPC + u;

    {
        float r = sigm(sum2(ar0) + br);
        float z = sigm(sum2(az0) + bz);
        float n = tanhf(sum2(anx0) + bxn + r * (sum2(anh0) + bhn));
        float hold = sm[OFF_HS + b0 * RSH + U];
        hout[(bg * BPC + b0) * HH + U] = (1.0f - z) * n + z * hold;
    }
    {
        float r = sigm(sum2(ar1) + br);
        float z = sigm(sum2(az1) + bz);
        float n = tanhf(sum2(anx1) + bxn + r * (sum2(anh1) + bhn));
        float hold = sm[OFF_HS + b1 * RSH + U];
        hout[(bg * BPC + b1) * HH + U] = (1.0f - z) * n + z * hold;
    }
}

// ---------------- the persistent kernel ----------------
__global__ void __launch_bounds__(NTHR, 1)
gruvae_kernel(const float* __restrict__ x,    const float* __restrict__ eps,
              const float* __restrict__ eWih, const float* __restrict__ eWhh,
              const float* __restrict__ ebih, const float* __restrict__ ebhh,
              const float* __restrict__ muW,  const float* __restrict__ mub,
              const float* __restrict__ lvW,  const float* __restrict__ lvb,
              const float* __restrict__ l2hW, const float* __restrict__ l2hb,
              const float* __restrict__ dWih, const float* __restrict__ dWhh,
              const float* __restrict__ dbih, const float* __restrict__ dbhh,
              const float* __restrict__ oW,   const float* __restrict__ ob,
              float* __restrict__ out)
{
    extern __shared__ float sm[];
    const int ug = blockIdx.x >> 2;   // 0..31 : unit group
    const int bg = blockIdx.x & 3;    // 0..3  : batch group
    const int tid = threadIdx.x;

    // ---- init: zero h0 slice and decoder feedback input ----
    {
        int u = tid & 15, bp = tid >> 4;
        int U = ug * UPC + u;
        g_h[0][bg * BPC + 2 * bp][U]     = 0.0f;
        g_h[0][bg * BPC + 2 * bp + 1][U] = 0.0f;
        if (tid < 32) ((float*)g_inp)[blockIdx.x * 32 + tid] = 0.0f;
    }
    load_gate_weights(sm, eWhh, eWih, ebih, ebhh, ug);
    grid_barrier();

    // ================= encoder scan =================
    for (int t = 0; t < TT; t++) {
        load_hs(sm, &g_h[t & 1][0][0], bg);
        load_xs(sm, x + t * II, TT * II, bg);
        __syncthreads();
        gru_compute_store(sm, &g_h[(t + 1) & 1][0][0], bg, ug);
        grid_barrier();
    }

    // ================= latent heads =================
    // final h_n lives in g_h[0] (TT even)
    load_hs(sm, &g_h[0][0][0], bg);
    __syncthreads();

    const int RECON = BB * TT * II;
    float mu_val;
    int lat, bglob;
    {
        int b = tid & 15, j = (tid >> 4) & 3, kind = tid >> 6;
        lat = ug * 4 + j;
        bglob = bg * BPC + b;
        const float* wrow = (kind ? lvW : muW) + lat * HH;
        const float* hsrow = sm + OFF_HS + b * RSH;
        const float4* w4 = (const float4*)wrow;
        float acc = 0.0f;
#pragma unroll 4
        for (int q = 0; q < HH / 4; q++) {
            float4 w = w4[q];
            acc += hsrow[4 * q] * w.x + hsrow[4 * q + 1] * w.y
                 + hsrow[4 * q + 2] * w.z + hsrow[4 * q + 3] * w.w;
        }
        acc += (kind ? lvb : mub)[lat];
        out[RECON + kind * BB * LL + bglob * LL + lat] = acc;   // mu then logvar
        if (kind) sm[OFF_RED + tid - 64] = acc;                 // hand logvar to mu thread
        mu_val = acc;
    }
    __syncthreads();
    if (tid < 64) {                                              // kind == 0 (mu) threads
        float lv = sm[OFF_RED + tid];
        g_z[bglob][lat] = mu_val + eps[bglob * LL + lat] * expf(0.5f * lv);
    }
    grid_barrier();

    // ================= h_dec = z @ l2h_W^T + b =================
    {
        float* zsm = sm + OFF_ZS;
        for (int idx = tid; idx < BPC * (LL / 4); idx += NTHR) {
            int b = idx >> 5, q = idx & 31;
            float4 v = reinterpret_cast<const float4*>(&g_z[bg * BPC + b][0])[q];
            float* d = zsm + b * RSZ + 4 * q;
            d[0] = v.x; d[1] = v.y; d[2] = v.z; d[3] = v.w;
        }
        __syncthreads();
        int u = tid & 15, bp = tid >> 4;
        int U = ug * UPC + u;
        const float4* w4 = (const float4*)(l2hW + U * LL);
        float a0 = 0.0f, a1 = 0.0f;
#pragma unroll 4
        for (int q = 0; q < LL / 4; q++) {
            float4 w = w4[q];
            const float* r0 = zsm + (2 * bp) * RSZ + 4 * q;
            const float* r1 = zsm + (2 * bp + 1) * RSZ + 4 * q;
            a0 += r0[0] * w.x + r0[1] * w.y + r0[2] * w.z + r0[3] * w.w;
            a1 += r1[0] * w.x + r1[1] * w.y + r1[2] * w.z + r1[3] * w.w;
        }
        float bias = l2hb[U];
        g_h[0][bg * BPC + 2 * bp][U]     = a0 + bias;
        g_h[0][bg * BPC + 2 * bp + 1][U] = a1 + bias;
    }
    __syncthreads();

    // ---- stage decoder weights + this CTA's 2 output rows ----
    load_gate_weights(sm, dWhh, dWih, dbih, dbhh, ug);
    {
        float* ows = sm + OFF_OW;
        for (int idx = tid; idx < 2 * HH; idx += NTHR) {
            int i = idx >> 9, k = idx & 511;
            ows[i * RSO + k] = oW[(ug * 2 + i) * HH + k];
        }
        if (tid < 2) sm[OFF_OB + tid] = ob[ug * 2 + tid];
    }
    grid_barrier();   // h_dec (all CTAs) + local staging complete

    load_hs(sm, &g_h[0][0][0], bg);   // smem hs := h_dec

    // ================= decoder scan =================
    for (int t = 0; t < TT; t++) {
        load_xs(sm, &g_inp[0][0], II, bg);
        __syncthreads();
        gru_compute_store(sm, &g_h[(t + 1) & 1][0][0], bg, ug);
        grid_barrier();

        load_hs(sm, &g_h[(t + 1) & 1][0][0], bg);   // full new h
        __syncthreads();

        // out_t = h_{t+1} @ oW^T + ob  (this CTA: 16 batches x 2 output cols)
        {
            int s = tid & 3, il = (tid >> 2) & 1, b = tid >> 3;
            const ull* hrow = (const ull*)(sm + OFF_HS + b * RSH);
            const ull* orow = (const ull*)(sm + OFF_OW + il * RSO);
            ull acc = 0;
#pragma unroll 8
            for (int j = 0; j < 64; j++) {
                int p = s + 4 * j;           // interleaved slices -> mild conflicts
                ffma2(acc, hrow[p], orow[p]);
            }
            float v = sum2(acc);
            v += __shfl_xor_sync(0xffffffffu, v, 1);
            v += __shfl_xor_sync(0xffffffffu, v, 2);
            if (s == 0) {
                int ig = ug * 2 + il;
                int bgl = bg * BPC + b;
                float val = v + sm[OFF_OB + il];
                out[(bgl * TT + t) * II + ig] = val;
                g_inp[bgl][ig] = val;
            }
        }
        grid_barrier();   // g_inp visible before next load_xs
        // smem hs already holds h_{t+1} for the next gru step
    }
}

extern "C" void kernel_launch(void* const* d_in, const int* in_sizes, int n_in,
                              void* d_out, int out_size) {
    (void)in_sizes; (void)n_in; (void)out_size;
    cudaFuncSetAttribute(gruvae_kernel,
                         cudaFuncAttributeMaxDynamicSharedMemorySize, SMEM_BYTES);
    gruvae_kernel<<<NCTA, NTHR, SMEM_BYTES>>>(
        (const float*)d_in[0],  (const float*)d_in[1],
        (const float*)d_in[2],  (const float*)d_in[3],
        (const float*)d_in[4],  (const float*)d_in[5],
        (const float*)d_in[6],  (const float*)d_in[7],
        (const float*)d_in[8],  (const float*)d_in[9],
        (const float*)d_in[10], (const float*)d_in[11],
        (const float*)d_in[12], (const float*)d_in[13],
        (const float*)d_in[14], (const float*)d_in[15],
        (const float*)d_in[16], (const float*)d_in[17],
        (float*)d_out);
}

// round 4
// speedup vs baseline: 1.0217x; 1.0217x over previous
#include <cuda_runtime.h>
#include <math.h>

// ---------------- problem constants ----------------
#define BB   64      // batch
#define TT   1024    // time steps
#define II   64      // input dim
#define HH   512     // hidden dim
#define LL   128     // latent dim

// ---------------- launch geometry ----------------
#define NCTA 128     // <= #SMs -> all CTAs co-resident -> grid barrier safe
#define NTHR 256     // 8 warps -> 2 per SMSP (latency hiding)
#define UPC  16      // units per CTA   (32 unit-groups)
#define BPC  16      // batches per CTA (4 batch-groups)

// ---------------- shared memory layout (floats) ----------------
// row strides mod 32 == 2 -> 16 unit rows hit distinct bank pairs
#define RSH 514
#define RSX 66
#define RSZ 130
#define RSO 514

#define OFF_WSH 0
#define SZ_WSH  (3*UPC*RSH)
#define OFF_WSX (OFF_WSH + SZ_WSH)
#define SZ_WSX  (3*UPC*RSX)
#define OFF_HS  (OFF_WSX + SZ_WSX)
#define SZ_HS   (BPC*RSH)
#define OFF_XS  (OFF_HS + SZ_HS)
#define SZ_XS   (BPC*RSX)
#define OFF_ZS  (OFF_XS + SZ_XS)
#define SZ_ZS   (BPC*RSZ)
#define OFF_OW  (OFF_ZS + SZ_ZS)
#define SZ_OW   (2*RSO)
#define OFF_BXS (OFF_OW + SZ_OW)
#define OFF_BHS (OFF_BXS + 48)
#define OFF_OB  (OFF_BHS + 48)
#define OFF_RED (OFF_OB + 8)
#define SZ_RED  (128*9)                  /* K-split partial sums, stride 9 = conflict-free */
#define SMEM_FLOATS (OFF_RED + SZ_RED)
#define SMEM_BYTES  (SMEM_FLOATS * 4)    /* ~166 KB -> 1 CTA/SM */

typedef unsigned long long ull;

// ---------------- device scratch ----------------
__device__ float g_h[2][BB][HH];
__device__ float g_inp[BB][II];
__device__ float g_z[BB][LL];
__device__ volatile unsigned g_flag[NCTA * 32];   // one 128B line per CTA
__device__ volatile unsigned g_gen = 0;

// ---------------- packed fp32x2 FMA ----------------
__device__ __forceinline__ void ffma2(ull& d, ull a, ull b) {
    asm("fma.rn.f32x2 %0, %1, %2, %0;" : "+l"(d) : "l"(a), "l"(b));
}
__device__ __forceinline__ float sum2(ull v) {
    return __uint_as_float((unsigned)v) + __uint_as_float((unsigned)(v >> 32));
}
__device__ __forceinline__ float sigm(float x) { return 1.0f / (1.0f + expf(-x)); }

// ---------------- flag-based grid barrier ----------------
// Arrivals are parallel STGs to per-CTA lines (no atomic serialization).
// CTA 0's threads poll all flags concurrently, then publish g_gen.
// Generations only increase -> safe across CUDA-graph replays.
__device__ __forceinline__ void grid_barrier(unsigned target) {
    __syncthreads();
    if (blockIdx.x == 0) {
        if (threadIdx.x > 0 && threadIdx.x < NCTA) {
            while (g_flag[threadIdx.x * 32] != target) { }
        }
        __syncthreads();
        if (threadIdx.x == 0) { __threadfence(); g_gen = target; }
        __threadfence();
        __syncthreads();
    } else {
        if (threadIdx.x == 0) {
            __threadfence();
            g_flag[blockIdx.x * 32] = target;
            while (g_gen != target) { }
            __threadfence();
        }
        __syncthreads();
    }
}

// ---------------- SMEM staging helpers ----------------
__device__ void load_gate_weights(float* sm, const float* W_hh, const float* W_ih,
                                  const float* b_ih, const float* b_hh, int ug) {
    float* wsh = sm + OFF_WSH;
    float* wsx = sm + OFF_WSX;
    for (int idx = threadIdx.x; idx < 48 * HH; idx += NTHR) {
        int r = idx >> 9, k = idx & 511;
        int g = r >> 4, u = r & 15;
        wsh[(g * UPC + u) * RSH + k] = W_hh[(g * HH + ug * UPC + u) * HH + k];
    }
    for (int idx = threadIdx.x; idx < 48 * II; idx += NTHR) {
        int r = idx >> 6, k = idx & 63;
        int g = r >> 4, u = r & 15;
        wsx[(g * UPC + u) * RSX + k] = W_ih[(g * HH + ug * UPC + u) * II + k];
    }
    if (threadIdx.x < 48) {
        int g = threadIdx.x >> 4, u = threadIdx.x & 15;
        sm[OFF_BXS + threadIdx.x] = b_ih[g * HH + ug * UPC + u];
        sm[OFF_BHS + threadIdx.x] = b_hh[g * HH + ug * UPC + u];
    }
}

__device__ void load_hs(float* sm, const float* hsrc, int bg) {
    float* hsm = sm + OFF_HS;
    for (int idx = threadIdx.x; idx < BPC * (HH / 4); idx += NTHR) {
        int b = idx >> 7, q = idx & 127;
        float4 v = reinterpret_cast<const float4*>(hsrc + (bg * BPC + b) * HH)[q];
        float* d = hsm + b * RSH + 4 * q;
        d[0] = v.x; d[1] = v.y; d[2] = v.z; d[3] = v.w;
    }
}

__device__ void load_xs(float* sm, const float* src, int rowstride, int bg) {
    float* xsm = sm + OFF_XS;
    for (int idx = threadIdx.x; idx < BPC * (II / 4); idx += NTHR) {
        int b = idx >> 4, q = idx & 15;
        float4 v = reinterpret_cast<const float4*>(src + (bg * BPC + b) * rowstride)[q];
        float* d = xsm + b * RSX + 4 * q;
        d[0] = v.x; d[1] = v.y; d[2] = v.z; d[3] = v.w;
    }
}

// ---------------- GRU step core (K-split across thread halves) ----------------
__device__ void gru_compute_store(float* sm, float* hout, int bg, int ug) {
    const int u  = threadIdx.x & 15;
    const int bp = (threadIdx.x >> 4) & 7;
    const int ks = threadIdx.x >> 7;          // K half
    const int b0 = 2 * bp, b1 = b0 + 1;

    const ull* wr = (const ull*)(sm + OFF_WSH + (0 * UPC + u) * RSH) + ks * (HH / 4);
    const ull* wz = (const ull*)(sm + OFF_WSH + (1 * UPC + u) * RSH) + ks * (HH / 4);
    const ull* wn = (const ull*)(sm + OFF_WSH + (2 * UPC + u) * RSH) + ks * (HH / 4);
    const ull* h0 = (const ull*)(sm + OFF_HS + b0 * RSH) + ks * (HH / 4);
    const ull* h1 = (const ull*)(sm + OFF_HS + b1 * RSH) + ks * (HH / 4);

    ull ar0 = 0, az0 = 0, anh0 = 0, anx0 = 0;
    ull ar1 = 0, az1 = 0, anh1 = 0, anx1 = 0;

#pragma unroll 4
    for (int p = 0; p < HH / 4; p++) {        // 128 iters (half of K)
        ull a = wr[p], c = wz[p], e = wn[p];
        ull x0 = h0[p], x1 = h1[p];
        ffma2(ar0, x0, a);  ffma2(ar1, x1, a);
        ffma2(az0, x0, c);  ffma2(az1, x1, c);
        ffma2(anh0, x0, e); ffma2(anh1, x1, e);
    }

    const ull* xr = (const ull*)(sm + OFF_WSX + (0 * UPC + u) * RSX) + ks * (II / 4);
    const ull* xz = (const ull*)(sm + OFF_WSX + (1 * UPC + u) * RSX) + ks * (II / 4);
    const ull* xn = (const ull*)(sm + OFF_WSX + (2 * UPC + u) * RSX) + ks * (II / 4);
    const ull* q0 = (const ull*)(sm + OFF_XS + b0 * RSX) + ks * (II / 4);
    const ull* q1 = (const ull*)(sm + OFF_XS + b1 * RSX) + ks * (II / 4);

#pragma unroll 4
    for (int p = 0; p < II / 4; p++) {        // 16 iters
        ull a = xr[p], c = xz[p], e = xn[p];
        ull x0 = q0[p], x1 = q1[p];
        ffma2(ar0, x0, a);  ffma2(ar1, x1, a);
        ffma2(az0, x0, c);  ffma2(az1, x1, c);
        ffma2(anx0, x0, e); ffma2(anx1, x1, e);
    }

    float s0 = sum2(ar0), s1 = sum2(az0), s2 = sum2(anh0), s3 = sum2(anx0);
    float s4 = sum2(ar1), s5 = sum2(az1), s6 = sum2(anh1), s7 = sum2(anx1);

    if (ks) {
        float* rd = sm + OFF_RED + (threadIdx.x - 128) * 9;
        rd[0] = s0; rd[1] = s1; rd[2] = s2; rd[3] = s3;
        rd[4] = s4; rd[5] = s5; rd[6] = s6; rd[7] = s7;
    }
    __syncthreads();
    if (!ks) {
        const float* rd = sm + OFF_RED + threadIdx.x * 9;
        s0 += rd[0]; s1 += rd[1]; s2 += rd[2]; s3 += rd[3];
        s4 += rd[4]; s5 += rd[5]; s6 += rd[6]; s7 += rd[7];

        const float br  = sm[OFF_BXS + u]      + sm[OFF_BHS + u];
        const float bz  = sm[OFF_BXS + 16 + u] + sm[OFF_BHS + 16 + u];
        const float bxn = sm[OFF_BXS + 32 + u];
        const float bhn = sm[OFF_BHS + 32 + u];
        const int U = ug * UPC + u;
        {
            float r = sigm(s0 + br);
            float z = sigm(s1 + bz);
            float n = tanhf(s3 + bxn + r * (s2 + bhn));
            float hold = sm[OFF_HS + b0 * RSH + U];
            hout[(bg * BPC + b0) * HH + U] = (1.0f - z) * n + z * hold;
        }
        {
            float r = sigm(s4 + br);
            float z = sigm(s5 + bz);
            float n = tanhf(s7 + bxn + r * (s6 + bhn));
            float hold = sm[OFF_HS + b1 * RSH + U];
            hout[(bg * BPC + b1) * HH + U] = (1.0f - z) * n + z * hold;
        }
    }
}

// ---------------- the persistent kernel ----------------
__global__ void __launch_bounds__(NTHR, 1)
gruvae_kernel(const float* __restrict__ x,    const float* __restrict__ eps,
              const float* __restrict__ eWih, const float* __restrict__ eWhh,
              const float* __restrict__ ebih, const float* __restrict__ ebhh,
              const float* __restrict__ muW,  const float* __restrict__ mub,
              const float* __restrict__ lvW,  const float* __restrict__ lvb,
              const float* __restrict__ l2hW, const float* __restrict__ l2hb,
              const float* __restrict__ dWih, const float* __restrict__ dWhh,
              const float* __restrict__ dbih, const float* __restrict__ dbhh,
              const float* __restrict__ oW,   const float* __restrict__ ob,
              float* __restrict__ out)
{
    extern __shared__ float sm[];
    const int ug = blockIdx.x >> 2;
    const int bg = blockIdx.x & 3;
    const int tid = threadIdx.x;

    unsigned gen = g_gen;           // replay-safe starting generation

    // ---- init: zero h0 slice and decoder feedback input ----
    {
        int u = tid & 15, b = tid >> 4;
        g_h[0][bg * BPC + b][ug * UPC + u] = 0.0f;
        if (tid < 32) ((float*)g_inp)[blockIdx.x * 32 + tid] = 0.0f;
    }
    load_gate_weights(sm, eWhh, eWih, ebih, ebhh, ug);
    grid_barrier(++gen);

    // ================= encoder scan =================
    for (int t = 0; t < TT; t++) {
        load_hs(sm, &g_h[t & 1][0][0], bg);
        load_xs(sm, x + t * II, TT * II, bg);
        __syncthreads();
        gru_compute_store(sm, &g_h[(t + 1) & 1][0][0], bg, ug);
        grid_barrier(++gen);
    }

    // ================= latent heads (h_n in g_h[0], TT even) =================
    load_hs(sm, &g_h[0][0][0], bg);
    __syncthreads();

    const int RECON = BB * TT * II;
    float mu_val = 0.0f;
    if (tid < 128) {
        int b = tid & 15, j = (tid >> 4) & 3, kind = tid >> 6;
        int lat = ug * 4 + j;
        int bglob = bg * BPC + b;
        const float4* w4 = (const float4*)((kind ? lvW : muW) + lat * HH);
        const float* hsrow = sm + OFF_HS + b * RSH;
        float acc = 0.0f;
#pragma unroll 4
        for (int q = 0; q < HH / 4; q++) {
            float4 w = w4[q];
            acc += hsrow[4 * q] * w.x + hsrow[4 * q + 1] * w.y
                 + hsrow[4 * q + 2] * w.z + hsrow[4 * q + 3] * w.w;
        }
        acc += (kind ? lvb : mub)[lat];
        out[RECON + kind * BB * LL + bglob * LL + lat] = acc;
        if (kind) sm[OFF_RED + (tid - 64)] = acc;   // hand logvar to mu thread
        mu_val = acc;
    }
    __syncthreads();
    if (tid < 64) {
        int b = tid & 15, j = tid >> 4;
        int lat = ug * 4 + j;
        int bglob = bg * BPC + b;
        float lv = sm[OFF_RED + tid];
        g_z[bglob][lat] = mu_val + eps[bglob * LL + lat] * expf(0.5f * lv);
    }
    grid_barrier(++gen);

    // ================= h_dec = z @ l2h_W^T + b =================
    {
        float* zsm = sm + OFF_ZS;
        for (int idx = tid; idx < BPC * (LL / 4); idx += NTHR) {
            int b = idx >> 5, q = idx & 31;
            float4 v = reinterpret_cast<const float4*>(&g_z[bg * BPC + b][0])[q];
            float* d = zsm + b * RSZ + 4 * q;
            d[0] = v.x; d[1] = v.y; d[2] = v.z; d[3] = v.w;
        }
        __syncthreads();
        int u = tid & 15, b = tid >> 4;
        int U = ug * UPC + u;
        const float4* w4 = (const float4*)(l2hW + U * LL);
        float a0 = 0.0f;
#pragma unroll 4
        for (int q = 0; q < LL / 4; q++) {
            float4 w = w4[q];
            const float* r0 = zsm + b * RSZ + 4 * q;
            a0 += r0[0] * w.x + r0[1] * w.y + r0[2] * w.z + r0[3] * w.w;
        }
        g_h[0][bg * BPC + b][U] = a0 + l2hb[U];
    }
    __syncthreads();

    // ---- stage decoder weights + this CTA's 2 output rows ----
    load_gate_weights(sm, dWhh, dWih, dbih, dbhh, ug);
    {
        float* ows = sm + OFF_OW;
        for (int idx = tid; idx < 2 * HH; idx += NTHR) {
            int i = idx >> 9, k = idx & 511;
            ows[i * RSO + k] = oW[(ug * 2 + i) * HH + k];
        }
        if (tid < 2) sm[OFF_OB + tid] = ob[ug * 2 + tid];
    }
    grid_barrier(++gen);

    load_hs(sm, &g_h[0][0][0], bg);   // smem hs := h_dec

    // ================= decoder scan =================
    for (int t = 0; t < TT; t++) {
        load_xs(sm, &g_inp[0][0], II, bg);
        __syncthreads();
        gru_compute_store(sm, &g_h[(t + 1) & 1][0][0], bg, ug);
        grid_barrier(++gen);

        load_hs(sm, &g_h[(t + 1) & 1][0][0], bg);   // full new h
        __syncthreads();

        // out_t = h_{t+1} @ oW^T + ob  (16 batches x 2 output cols per CTA)
        {
            int s = tid & 7, il = (tid >> 3) & 1, b = tid >> 4;
            const ull* hrow = (const ull*)(sm + OFF_HS + b * RSH);
            const ull* orow = (const ull*)(sm + OFF_OW + il * RSO);
            ull acc = 0;
#pragma unroll 8
            for (int j = 0; j < 32; j++) {
                int p = s + 8 * j;
                ffma2(acc, hrow[p], orow[p]);
            }
            float v = sum2(acc);
            v += __shfl_xor_sync(0xffffffffu, v, 1);
            v += __shfl_xor_sync(0xffffffffu, v, 2);
            v += __shfl_xor_sync(0xffffffffu, v, 4);
            if (s == 0) {
                int ig = ug * 2 + il;
                int bgl = bg * BPC + b;
                float val = v + sm[OFF_OB + il];
                out[(bgl * TT + t) * II + ig] = val;
                g_inp[bgl][ig] = val;
            }
        }
        grid_barrier(++gen);   // g_inp visible before next load_xs
        // smem hs already holds h_{t+1} for the next gru step
    }
}

extern "C" void kernel_launch(void* const* d_in, const int* in_sizes, int n_in,
                              void* d_out, int out_size) {
    (void)in_sizes; (void)n_in; (void)out_size;
    cudaFuncSetAttribute(gruvae_kernel,
                         cudaFuncAttributeMaxDynamicSharedMemorySize, SMEM_BYTES);
    gruvae_kernel<<<NCTA, NTHR, SMEM_BYTES>>>(
        (const float*)d_in[0],  (const float*)d_in[1],
        (const float*)d_in[2],  (const float*)d_in[3],
        (const float*)d_in[4],  (const float*)d_in[5],
        (const float*)d_in[6],  (const float*)d_in[7],
        (const float*)d_in[8],  (const float*)d_in[9],
        (const float*)d_in[10], (const float*)d_in[11],
        (const float*)d_in[12], (const float*)d_in[13],
        (const float*)d_in[14], (const float*)d_in[15],
        (const float*)d_in[16], (const float*)d_in[17],
        (float*)d_out);
}

// round 5
// speedup vs baseline: 1.0617x; 1.0392x over previous
#include <cuda_runtime.h>
#include <math.h>

// ---------------- problem constants ----------------
#define BB   64      // batch
#define TT   1024    // time steps
#define II   64      // input dim
#define HH   512     // hidden dim
#define LL   128     // latent dim

// ---------------- launch geometry ----------------
#define NCTA 128     // <= #SMs -> all CTAs co-resident -> grid barrier safe
#define NTHR 256     // 8 warps -> 2 per SMSP (latency hiding)
#define UPC  16      // units per CTA   (32 unit-groups)
#define BPC  16      // batches per CTA (4 batch-groups)

// ---------------- shared memory layout (floats) ----------------
// row strides mod 32 == 2 -> 16 unit rows hit distinct bank pairs
#define RSH 514
#define RSX 66
#define RSZ 130
#define RSO 514

#define OFF_WSH 0
#define SZ_WSH  (3*UPC*RSH)
#define OFF_WSX (OFF_WSH + SZ_WSH)
#define SZ_WSX  (3*UPC*RSX)
#define OFF_HS  (OFF_WSX + SZ_WSX)
#define SZ_HS   (BPC*RSH)
#define OFF_XS  (OFF_HS + SZ_HS)
#define SZ_XS   (BPC*RSX)
#define OFF_ZS  (OFF_XS + SZ_XS)
#define SZ_ZS   (BPC*RSZ)
#define OFF_OW  (OFF_ZS + SZ_ZS)
#define SZ_OW   (2*RSO)
#define OFF_BXS (OFF_OW + SZ_OW)
#define OFF_BHS (OFF_BXS + 48)
#define OFF_OB  (OFF_BHS + 48)
#define OFF_RED (OFF_OB + 8)
#define SZ_RED  (128*9)                  /* K-split partial sums, stride 9 = conflict-free */
#define SMEM_FLOATS (OFF_RED + SZ_RED)
#define SMEM_BYTES  (SMEM_FLOATS * 4)    /* ~166 KB -> 1 CTA/SM */

typedef unsigned long long ull;

// ---------------- device scratch ----------------
__device__ float g_h[2][BB][HH];
__device__ float g_inp[BB][II];
__device__ float g_z[BB][LL];
__device__ volatile unsigned g_flag[NCTA * 32];   // one 128B line per CTA
__device__ volatile unsigned g_gen = 0;

// ---------------- packed fp32x2 FMA ----------------
__device__ __forceinline__ void ffma2(ull& d, ull a, ull b) {
    asm("fma.rn.f32x2 %0, %1, %2, %0;" : "+l"(d) : "l"(a), "l"(b));
}
__device__ __forceinline__ float sum2(ull v) {
    return __uint_as_float((unsigned)v) + __uint_as_float((unsigned)(v >> 32));
}
__device__ __forceinline__ float sigm(float x) { return 1.0f / (1.0f + expf(-x)); }

// ---------------- flag-based grid barrier ----------------
// Arrivals are parallel STGs to per-CTA lines (no atomic serialization).
// CTA 0's threads poll all flags concurrently, then publish g_gen.
// Generations only increase -> safe across CUDA-graph replays.
__device__ __forceinline__ void grid_barrier(unsigned target) {
    __syncthreads();
    if (blockIdx.x == 0) {
        if (threadIdx.x > 0 && threadIdx.x < NCTA) {
            while (g_flag[threadIdx.x * 32] != target) { }
        }
        __syncthreads();
        if (threadIdx.x == 0) { __threadfence(); g_gen = target; }
        __threadfence();
        __syncthreads();
    } else {
        if (threadIdx.x == 0) {
            __threadfence();
            g_flag[blockIdx.x * 32] = target;
            while (g_gen != target) { }
            __threadfence();
        }
        __syncthreads();
    }
}

// ---------------- SMEM staging helpers ----------------
__device__ void load_gate_weights(float* sm, const float* W_hh, const float* W_ih,
                                  const float* b_ih, const float* b_hh, int ug) {
    float* wsh = sm + OFF_WSH;
    float* wsx = sm + OFF_WSX;
    for (int idx = threadIdx.x; idx < 48 * HH; idx += NTHR) {
        int r = idx >> 9, k = idx & 511;
        int g = r >> 4, u = r & 15;
        wsh[(g * UPC + u) * RSH + k] = W_hh[(g * HH + ug * UPC + u) * HH + k];
    }
    for (int idx = threadIdx.x; idx < 48 * II; idx += NTHR) {
        int r = idx >> 6, k = idx & 63;
        int g = r >> 4, u = r & 15;
        wsx[(g * UPC + u) * RSX + k] = W_ih[(g * HH + ug * UPC + u) * II + k];
    }
    if (threadIdx.x < 48) {
        int g = threadIdx.x >> 4, u = threadIdx.x & 15;
        sm[OFF_BXS + threadIdx.x] = b_ih[g * HH + ug * UPC + u];
        sm[OFF_BHS + threadIdx.x] = b_hh[g * HH + ug * UPC + u];
    }
}

__device__ void load_hs(float* sm, const float* hsrc, int bg) {
    float* hsm = sm + OFF_HS;
    for (int idx = threadIdx.x; idx < BPC * (HH / 4); idx += NTHR) {
        int b = idx >> 7, q = idx & 127;
        float4 v = reinterpret_cast<const float4*>(hsrc + (bg * BPC + b) * HH)[q];
        float* d = hsm + b * RSH + 4 * q;
        d[0] = v.x; d[1] = v.y; d[2] = v.z; d[3] = v.w;
    }
}

__device__ void load_xs(float* sm, const float* src, int rowstride, int bg) {
    float* xsm = sm + OFF_XS;
    for (int idx = threadIdx.x; idx < BPC * (II / 4); idx += NTHR) {
        int b = idx >> 4, q = idx & 15;
        float4 v = reinterpret_cast<const float4*>(src + (bg * BPC + b) * rowstride)[q];
        float* d = xsm + b * RSX + 4 * q;
        d[0] = v.x; d[1] = v.y; d[2] = v.z; d[3] = v.w;
    }
}

// ---------------- GRU step core (K-split across thread halves) ----------------
__device__ void gru_compute_store(float* sm, float* hout, int bg, int ug) {
    const int u  = threadIdx.x & 15;
    const int bp = (threadIdx.x >> 4) & 7;
    const int ks = threadIdx.x >> 7;          // K half
    const int b0 = 2 * bp, b1 = b0 + 1;

    const ull* wr = (const ull*)(sm + OFF_WSH + (0 * UPC + u) * RSH) + ks * (HH / 4);
    const ull* wz = (const ull*)(sm + OFF_WSH + (1 * UPC + u) * RSH) + ks * (HH / 4);
    const ull* wn = (const ull*)(sm + OFF_WSH + (2 * UPC + u) * RSH) + ks * (HH / 4);
    const ull* h0 = (const ull*)(sm + OFF_HS + b0 * RSH) + ks * (HH / 4);
    const ull* h1 = (const ull*)(sm + OFF_HS + b1 * RSH) + ks * (HH / 4);

    ull ar0 = 0, az0 = 0, anh0 = 0, anx0 = 0;
    ull ar1 = 0, az1 = 0, anh1 = 0, anx1 = 0;

#pragma unroll 4
    for (int p = 0; p < HH / 4; p++) {        // 128 iters (half of K)
        ull a = wr[p], c = wz[p], e = wn[p];
        ull x0 = h0[p], x1 = h1[p];
        ffma2(ar0, x0, a);  ffma2(ar1, x1, a);
        ffma2(az0, x0, c);  ffma2(az1, x1, c);
        ffma2(anh0, x0, e); ffma2(anh1, x1, e);
    }

    const ull* xr = (const ull*)(sm + OFF_WSX + (0 * UPC + u) * RSX) + ks * (II / 4);
    const ull* xz = (const ull*)(sm + OFF_WSX + (1 * UPC + u) * RSX) + ks * (II / 4);
    const ull* xn = (const ull*)(sm + OFF_WSX + (2 * UPC + u) * RSX) + ks * (II / 4);
    const ull* q0 = (const ull*)(sm + OFF_XS + b0 * RSX) + ks * (II / 4);
    const ull* q1 = (const ull*)(sm + OFF_XS + b1 * RSX) + ks * (II / 4);

#pragma unroll 4
    for (int p = 0; p < II / 4; p++) {        // 16 iters
        ull a = xr[p], c = xz[p], e = xn[p];
        ull x0 = q0[p], x1 = q1[p];
        ffma2(ar0, x0, a);  ffma2(ar1, x1, a);
        ffma2(az0, x0, c);  ffma2(az1, x1, c);
        ffma2(anx0, x0, e); ffma2(anx1, x1, e);
    }

    float s0 = sum2(ar0), s1 = sum2(az0), s2 = sum2(anh0), s3 = sum2(anx0);
    float s4 = sum2(ar1), s5 = sum2(az1), s6 = sum2(anh1), s7 = sum2(anx1);

    if (ks) {
        float* rd = sm + OFF_RED + (threadIdx.x - 128) * 9;
        rd[0] = s0; rd[1] = s1; rd[2] = s2; rd[3] = s3;
        rd[4] = s4; rd[5] = s5; rd[6] = s6; rd[7] = s7;
    }
    __syncthreads();
    if (!ks) {
        const float* rd = sm + OFF_RED + threadIdx.x * 9;
        s0 += rd[0]; s1 += rd[1]; s2 += rd[2]; s3 += rd[3];
        s4 += rd[4]; s5 += rd[5]; s6 += rd[6]; s7 += rd[7];

        const float br  = sm[OFF_BXS + u]      + sm[OFF_BHS + u];
        const float bz  = sm[OFF_BXS + 16 + u] + sm[OFF_BHS + 16 + u];
        const float bxn = sm[OFF_BXS + 32 + u];
        const float bhn = sm[OFF_BHS + 32 + u];
        const int U = ug * UPC + u;
        {
            float r = sigm(s0 + br);
            float z = sigm(s1 + bz);
            float n = tanhf(s3 + bxn + r * (s2 + bhn));
            float hold = sm[OFF_HS + b0 * RSH + U];
            hout[(bg * BPC + b0) * HH + U] = (1.0f - z) * n + z * hold;
        }
        {
            float r = sigm(s4 + br);
            float z = sigm(s5 + bz);
            float n = tanhf(s7 + bxn + r * (s6 + bhn));
            float hold = sm[OFF_HS + b1 * RSH + U];
            hout[(bg * BPC + b1) * HH + U] = (1.0f - z) * n + z * hold;
        }
    }
}

// ---------------- the persistent kernel ----------------
__global__ void __launch_bounds__(NTHR, 1)
gruvae_kernel(const float* __restrict__ x,    const float* __restrict__ eps,
              const float* __restrict__ eWih, const float* __restrict__ eWhh,
              const float* __restrict__ ebih, const float* __restrict__ ebhh,
              const float* __restrict__ muW,  const float* __restrict__ mub,
              const float* __restrict__ lvW,  const float* __restrict__ lvb,
              const float* __restrict__ l2hW, const float* __restrict__ l2hb,
              const float* __restrict__ dWih, const float* __restrict__ dWhh,
              const float* __restrict__ dbih, const float* __restrict__ dbhh,
              const float* __restrict__ oW,   const float* __restrict__ ob,
              float* __restrict__ out)
{
    extern __shared__ float sm[];
    const int ug = blockIdx.x >> 2;
    const int bg = blockIdx.x & 3;
    const int tid = threadIdx.x;

    unsigned gen = g_gen;           // replay-safe starting generation

    // ---- init: zero h0 slice and decoder feedback input ----
    {
        int u = tid & 15, b = tid >> 4;
        g_h[0][bg * BPC + b][ug * UPC + u] = 0.0f;
        if (tid < 32) ((float*)g_inp)[blockIdx.x * 32 + tid] = 0.0f;
    }
    load_gate_weights(sm, eWhh, eWih, ebih, ebhh, ug);
    grid_barrier(++gen);

    // ================= encoder scan =================
    for (int t = 0; t < TT; t++) {
        load_hs(sm, &g_h[t & 1][0][0], bg);
        load_xs(sm, x + t * II, TT * II, bg);
        __syncthreads();
        gru_compute_store(sm, &g_h[(t + 1) & 1][0][0], bg, ug);
        grid_barrier(++gen);
    }

    // ================= latent heads (h_n in g_h[0], TT even) =================
    load_hs(sm, &g_h[0][0][0], bg);
    __syncthreads();

    const int RECON = BB * TT * II;
    float mu_val = 0.0f;
    if (tid < 128) {
        int b = tid & 15, j = (tid >> 4) & 3, kind = tid >> 6;
        int lat = ug * 4 + j;
        int bglob = bg * BPC + b;
        const float4* w4 = (const float4*)((kind ? lvW : muW) + lat * HH);
        const float* hsrow = sm + OFF_HS + b * RSH;
        float acc = 0.0f;
#pragma unroll 4
        for (int q = 0; q < HH / 4; q++) {
            float4 w = w4[q];
            acc += hsrow[4 * q] * w.x + hsrow[4 * q + 1] * w.y
                 + hsrow[4 * q + 2] * w.z + hsrow[4 * q + 3] * w.w;
        }
        acc += (kind ? lvb : mub)[lat];
        out[RECON + kind * BB * LL + bglob * LL + lat] = acc;
        if (kind) sm[OFF_RED + (tid - 64)] = acc;   // hand logvar to mu thread
        mu_val = acc;
    }
    __syncthreads();
    if (tid < 64) {
        int b = tid & 15, j = tid >> 4;
        int lat = ug * 4 + j;
        int bglob = bg * BPC + b;
        float lv = sm[OFF_RED + tid];
        g_z[bglob][lat] = mu_val + eps[bglob * LL + lat] * expf(0.5f * lv);
    }
    grid_barrier(++gen);

    // ================= h_dec = z @ l2h_W^T + b =================
    {
        float* zsm = sm + OFF_ZS;
        for (int idx = tid; idx < BPC * (LL / 4); idx += NTHR) {
            int b = idx >> 5, q = idx & 31;
            float4 v = reinterpret_cast<const float4*>(&g_z[bg * BPC + b][0])[q];
            float* d = zsm + b * RSZ + 4 * q;
            d[0] = v.x; d[1] = v.y; d[2] = v.z; d[3] = v.w;
        }
        __syncthreads();
        int u = tid & 15, b = tid >> 4;
        int U = ug * UPC + u;
        const float4* w4 = (const float4*)(l2hW + U * LL);
        float a0 = 0.0f;
#pragma unroll 4
        for (int q = 0; q < LL / 4; q++) {
            float4 w = w4[q];
            const float* r0 = zsm + b * RSZ + 4 * q;
            a0 += r0[0] * w.x + r0[1] * w.y + r0[2] * w.z + r0[3] * w.w;
        }
        g_h[0][bg * BPC + b][U] = a0 + l2hb[U];
    }
    __syncthreads();

    // ---- stage decoder weights + this CTA's 2 output rows ----
    load_gate_weights(sm, dWhh, dWih, dbih, dbhh, ug);
    {
        float* ows = sm + OFF_OW;
        for (int idx = tid; idx < 2 * HH; idx += NTHR) {
            int i = idx >> 9, k = idx & 511;
            ows[i * RSO + k] = oW[(ug * 2 + i) * HH + k];
        }
        if (tid < 2) sm[OFF_OB + tid] = ob[ug * 2 + tid];
    }
    grid_barrier(++gen);

    load_hs(sm, &g_h[0][0][0], bg);   // smem hs := h_dec

    // ================= decoder scan =================
    for (int t = 0; t < TT; t++) {
        load_xs(sm, &g_inp[0][0], II, bg);
        __syncthreads();
        gru_compute_store(sm, &g_h[(t + 1) & 1][0][0], bg, ug);
        grid_barrier(++gen);

        load_hs(sm, &g_h[(t + 1) & 1][0][0], bg);   // full new h
        __syncthreads();

        // out_t = h_{t+1} @ oW^T + ob  (16 batches x 2 output cols per CTA)
        {
            int s = tid & 7, il = (tid >> 3) & 1, b = tid >> 4;
            const ull* hrow = (const ull*)(sm + OFF_HS + b * RSH);
            const ull* orow = (const ull*)(sm + OFF_OW + il * RSO);
            ull acc = 0;
#pragma unroll 8
            for (int j = 0; j < 32; j++) {
                int p = s + 8 * j;
                ffma2(acc, hrow[p], orow[p]);
            }
            float v = sum2(acc);
            v += __shfl_xor_sync(0xffffffffu, v, 1);
            v += __shfl_xor_sync(0xffffffffu, v, 2);
            v += __shfl_xor_sync(0xffffffffu, v, 4);
            if (s == 0) {
                int ig = ug * 2 + il;
                int bgl = bg * BPC + b;
                float val = v + sm[OFF_OB + il];
                out[(bgl * TT + t) * II + ig] = val;
                g_inp[bgl][ig] = val;
            }
        }
        grid_barrier(++gen);   // g_inp visible before next load_xs
        // smem hs already holds h_{t+1} for the next gru step
    }
}

extern "C" void kernel_launch(void* const* d_in, const int* in_sizes, int n_in,
                              void* d_out, int out_size) {
    (void)in_sizes; (void)n_in; (void)out_size;
    cudaFuncSetAttribute(gruvae_kernel,
                         cudaFuncAttributeMaxDynamicSharedMemorySize, SMEM_BYTES);
    gruvae_kernel<<<NCTA, NTHR, SMEM_BYTES>>>(
        (const float*)d_in[0],  (const float*)d_in[1],
        (const float*)d_in[2],  (const float*)d_in[3],
        (const float*)d_in[4],  (const float*)d_in[5],
        (const float*)d_in[6],  (const float*)d_in[7],
        (const float*)d_in[8],  (const float*)d_in[9],
        (const float*)d_in[10], (const float*)d_in[11],
        (const float*)d_in[12], (const float*)d_in[13],
        (const float*)d_in[14], (const float*)d_in[15],
        (const float*)d_in[16], (const float*)d_in[17],
        (float*)d_out);
}

// round 6
// speedup vs baseline: 1.4424x; 1.3586x over previous
#include <cuda_runtime.h>
#include <math.h>

#define BB 64
#define TT 1024
#define II 64
#define HH 512
#define LL 128

#define NCTA 128
#define NTHR 256

// smem layout (float offsets); strides 16B-aligned
#define RSH 520
#define RSX 68
#define RSZ 132
#define RSO 520
#define OFF_HS 0
#define OFF_XS (OFF_HS + 16*RSH)          /* 8320 */
#define OFF_ZS (OFF_XS + 16*RSX)          /* 9408 */
#define OFF_OW (OFF_ZS + 16*RSZ)          /* 11520 */
#define OFF_OB (OFF_OW + 2*RSO)           /* 12560 */
#define OFF_B  (OFF_OB + 16)              /* 12576: br,bz,bnx,bnh x16 */
#define OFF_SC (OFF_B + 64)               /* 12640 */
#define SZ_SC  (128*69 + 80)
#define SMEM_FLOATS (OFF_SC + SZ_SC)
#define SMEM_BYTES  (SMEM_FLOATS*4)       /* ~86 KB */

typedef unsigned long long ull;

__device__ float g_h[2][BB][HH];
__device__ float g_inp[BB][II];
__device__ float g_z[BB][LL];
__device__ volatile unsigned g_flag[NCTA * 32];

__device__ __forceinline__ void ffma2(ull& d, ull a, ull b) {
    asm("fma.rn.f32x2 %0, %1, %2, %0;" : "+l"(d) : "l"(a), "l"(b));
}
__device__ __forceinline__ float sum2(ull v) {
    return __uint_as_float((unsigned)v) + __uint_as_float((unsigned)(v >> 32));
}
__device__ __forceinline__ float sigm(float x) { return 1.0f / (1.0f + expf(-x)); }

// symmetric flag barrier: monotone counters -> graph-replay safe; wrap-safe compare
__device__ __forceinline__ void barrier(unsigned target) {
    __syncthreads();
    if (threadIdx.x == 0) { __threadfence(); g_flag[blockIdx.x * 32] = target; }
    if (threadIdx.x < NCTA) {
        while ((int)(g_flag[threadIdx.x * 32] - target) < 0) { }
        __threadfence();
    }
    __syncthreads();
}

__device__ __forceinline__ void load_hs(float* sm, const float* hsrc, int bg) {
    for (int idx = threadIdx.x; idx < 16 * (HH / 4); idx += NTHR) {
        int b = idx >> 7, q = idx & 127;
        float4 v = reinterpret_cast<const float4*>(hsrc + (bg * 16 + b) * HH)[q];
        float* d = sm + OFF_HS + b * RSH + 4 * q;
        d[0] = v.x; d[1] = v.y; d[2] = v.z; d[3] = v.w;
    }
}
__device__ __forceinline__ void load_xs(float* sm, const float* src, int rs, int bg) {
    for (int idx = threadIdx.x; idx < 16 * (II / 4); idx += NTHR) {
        int b = idx >> 4, q = idx & 15;
        float4 v = reinterpret_cast<const float4*>(src + (bg * 16 + b) * rs)[q];
        float* d = sm + OFF_XS + b * RSX + 4 * q;
        d[0] = v.x; d[1] = v.y; d[2] = v.z; d[3] = v.w;
    }
}

// stage per-phase weights into registers + biases into smem
__device__ __forceinline__ void load_wregs(
    const float* Whh, const float* Wih, const float* bih, const float* bhh,
    float* sm, int ug,
    ull (&whr)[16], ull (&whz)[16], ull (&whn)[16],
    ull (&wxr)[2],  ull (&wxz)[2],  ull (&wxn)[2])
{
    const int tid = threadIdx.x, u = tid & 15, ks = tid >> 4;
    const int row = ug * 16 + u;
#pragma unroll
    for (int p = 0; p < 16; p++) {
        whr[p] = *(const ull*)(Whh + (0 * HH + row) * HH + ks * 32 + 2 * p);
        whz[p] = *(const ull*)(Whh + (1 * HH + row) * HH + ks * 32 + 2 * p);
        whn[p] = *(const ull*)(Whh + (2 * HH + row) * HH + ks * 32 + 2 * p);
    }
#pragma unroll
    for (int p = 0; p < 2; p++) {
        wxr[p] = *(const ull*)(Wih + (0 * HH + row) * II + ks * 4 + 2 * p);
        wxz[p] = *(const ull*)(Wih + (1 * HH + row) * II + ks * 4 + 2 * p);
        wxn[p] = *(const ull*)(Wih + (2 * HH + row) * II + ks * 4 + 2 * p);
    }
    if (tid < 16) {
        sm[OFF_B + tid]      = bih[ug * 16 + tid] + bhh[ug * 16 + tid];
        sm[OFF_B + 16 + tid] = bih[HH + ug * 16 + tid] + bhh[HH + ug * 16 + tid];
        sm[OFF_B + 32 + tid] = bih[2 * HH + ug * 16 + tid];
        sm[OFF_B + 48 + tid] = bhh[2 * HH + ug * 16 + tid];
    }
}

// one GRU step: HS(h_t) + XS(x_t) in smem, weights in regs, h_{t+1} -> hout
__device__ __forceinline__ void gru_step(
    float* sm, float* hout, int bg, int ug,
    ull (&whr)[16], ull (&whz)[16], ull (&whn)[16],
    ull (&wxr)[2],  ull (&wxz)[2],  ull (&wxn)[2])
{
    const int tid = threadIdx.x, u = tid & 15, ks = tid >> 4, k0 = ks * 32;
#pragma unroll
    for (int bh = 0; bh < 2; bh++) {
        ull ar[8], az[8], an[8], ax[8];
#pragma unroll
        for (int j = 0; j < 8; j++) { ar[j] = az[j] = an[j] = ax[j] = 0ull; }
#pragma unroll
        for (int p = 0; p < 16; p++) {
            ull a = whr[p], c = whz[p], e = whn[p];
#pragma unroll
            for (int j = 0; j < 8; j++) {
                ull hv = *(const ull*)(sm + OFF_HS + (bh * 8 + j) * RSH + k0 + 2 * p);
                ffma2(ar[j], hv, a); ffma2(az[j], hv, c); ffma2(an[j], hv, e);
            }
        }
#pragma unroll
        for (int p = 0; p < 2; p++) {
            ull a = wxr[p], c = wxz[p], e = wxn[p];
#pragma unroll
            for (int j = 0; j < 8; j++) {
                ull xv = *(const ull*)(sm + OFF_XS + (bh * 8 + j) * RSX + ks * 4 + 2 * p);
                ffma2(ar[j], xv, a); ffma2(az[j], xv, c); ffma2(ax[j], xv, e);
            }
        }
#pragma unroll
        for (int j = 0; j < 8; j++) {
            float* d = sm + OFF_SC + (j * 16 + u) * 69 + ks;
            d[0]  = sum2(ar[j]);
            d[17] = sum2(az[j]);
            d[34] = sum2(an[j]);
            d[51] = sum2(ax[j]);
        }
        __syncthreads();
        if (tid < 128) {
            int uu = tid & 15, j = tid >> 4;
            const float* s = sm + OFF_SC + (j * 16 + uu) * 69;
            float s0 = 0, s1 = 0, s2 = 0, s3 = 0;
#pragma unroll
            for (int q = 0; q < 16; q++) {
                s0 += s[q]; s1 += s[17 + q]; s2 += s[34 + q]; s3 += s[51 + q];
            }
            int b = bh * 8 + j;
            float r = sigm(s0 + sm[OFF_B + uu]);
            float z = sigm(s1 + sm[OFF_B + 16 + uu]);
            float n = tanhf(s3 + sm[OFF_B + 32 + uu] + r * (s2 + sm[OFF_B + 48 + uu]));
            float hold = sm[OFF_HS + b * RSH + ug * 16 + uu];
            hout[(bg * 16 + b) * HH + ug * 16 + uu] = (1.0f - z) * n + z * hold;
        }
        __syncthreads();
    }
}

__global__ void __launch_bounds__(NTHR, 1)
gruvae_kernel(const float* __restrict__ x,    const float* __restrict__ eps,
              const float* __restrict__ eWih, const float* __restrict__ eWhh,
              const float* __restrict__ ebih, const float* __restrict__ ebhh,
              const float* __restrict__ muW,  const float* __restrict__ mub,
              const float* __restrict__ lvW,  const float* __restrict__ lvb,
              const float* __restrict__ l2hW, const float* __restrict__ l2hb,
              const float* __restrict__ dWih, const float* __restrict__ dWhh,
              const float* __restrict__ dbih, const float* __restrict__ dbhh,
              const float* __restrict__ oW,   const float* __restrict__ ob,
              float* __restrict__ out)
{
    extern __shared__ float sm[];
    const int ug = blockIdx.x >> 2, bg = blockIdx.x & 3, tid = threadIdx.x;
    unsigned gen = g_flag[blockIdx.x * 32];

    ull whr[16], whz[16], whn[16], wxr[2], wxz[2], wxn[2];

    // init: zero h0 slice + decoder feedback input; stage encoder weights
    {
        int u = tid & 15, b = tid >> 4;
        g_h[0][bg * 16 + b][ug * 16 + u] = 0.0f;
        if (tid < 32) ((float*)g_inp)[blockIdx.x * 32 + tid] = 0.0f;
    }
    load_wregs(eWhh, eWih, ebih, ebhh, sm, ug, whr, whz, whn, wxr, wxz, wxn);
    barrier(++gen);

    // ===== encoder =====
    for (int t = 0; t < TT; t++) {
        load_hs(sm, &g_h[t & 1][0][0], bg);
        load_xs(sm, x + t * II, TT * II, bg);
        __syncthreads();
        gru_step(sm, &g_h[(t + 1) & 1][0][0], bg, ug, whr, whz, whn, wxr, wxz, wxn);
        barrier(++gen);
    }

    // ===== latent heads (h_n in g_h[0]) =====
    load_hs(sm, &g_h[0][0][0], bg);
    __syncthreads();
    const int RECON = BB * TT * II;
    float mu_val = 0.0f;
    if (tid < 128) {
        int b = tid & 15, j = (tid >> 4) & 3, kind = tid >> 6;
        int lat = ug * 4 + j, bglob = bg * 16 + b;
        const float4* w4 = (const float4*)((kind ? lvW : muW) + lat * HH);
        const float* hr = sm + OFF_HS + b * RSH;
        float acc = 0.0f;
#pragma unroll 4
        for (int q = 0; q < HH / 4; q++) {
            float4 w = w4[q];
            acc += hr[4*q]*w.x + hr[4*q+1]*w.y + hr[4*q+2]*w.z + hr[4*q+3]*w.w;
        }
        acc += (kind ? lvb : mub)[lat];
        out[RECON + kind * BB * LL + bglob * LL + lat] = acc;
        if (kind) sm[OFF_SC + (tid - 64)] = acc;
        mu_val = acc;
    }
    __syncthreads();
    if (tid < 64) {
        int b = tid & 15, j = tid >> 4;
        int lat = ug * 4 + j, bglob = bg * 16 + b;
        g_z[bglob][lat] = mu_val + eps[bglob * LL + lat] * expf(0.5f * sm[OFF_SC + tid]);
    }
    barrier(++gen);

    // ===== h_dec = z @ l2hW^T + b =====
    {
        for (int idx = tid; idx < 16 * (LL / 4); idx += NTHR) {
            int b = idx >> 5, q = idx & 31;
            float4 v = reinterpret_cast<const float4*>(&g_z[bg * 16 + b][0])[q];
            float* d = sm + OFF_ZS + b * RSZ + 4 * q;
            d[0] = v.x; d[1] = v.y; d[2] = v.z; d[3] = v.w;
        }
        __syncthreads();
        int u = tid & 15, b = tid >> 4;
        int U = ug * 16 + u;
        const float4* w4 = (const float4*)(l2hW + U * LL);
        float a0 = 0.0f;
#pragma unroll 4
        for (int q = 0; q < LL / 4; q++) {
            float4 w = w4[q];
            const float* r0 = sm + OFF_ZS + b * RSZ + 4 * q;
            a0 += r0[0]*w.x + r0[1]*w.y + r0[2]*w.z + r0[3]*w.w;
        }
        g_h[0][bg * 16 + b][U] = a0 + l2hb[U];
    }
    __syncthreads();

    // stage decoder weights + output rows
    load_wregs(dWhh, dWih, dbih, dbhh, sm, ug, whr, whz, whn, wxr, wxz, wxn);
    for (int idx = tid; idx < 2 * HH; idx += NTHR) {
        int i = idx >> 9, k = idx & 511;
        sm[OFF_OW + i * RSO + k] = oW[(ug * 2 + i) * HH + k];
    }
    if (tid < 2) sm[OFF_OB + tid] = ob[ug * 2 + tid];
    barrier(++gen);

    load_hs(sm, &g_h[0][0][0], bg);   // HS := h_dec

    // ===== decoder =====
    for (int t = 0; t < TT; t++) {
        load_xs(sm, &g_inp[0][0], II, bg);
        __syncthreads();
        gru_step(sm, &g_h[(t + 1) & 1][0][0], bg, ug, whr, whz, whn, wxr, wxz, wxn);
        barrier(++gen);

        load_hs(sm, &g_h[(t + 1) & 1][0][0], bg);   // full new h (stays for next step)
        __syncthreads();
        {
            int s = tid & 7, il = (tid >> 3) & 1, b = tid >> 4;
            const ull* hrow = (const ull*)(sm + OFF_HS + b * RSH);
            const ull* orow = (const ull*)(sm + OFF_OW + il * RSO);
            ull acc = 0;
#pragma unroll 8
            for (int j = 0; j < 32; j++) ffma2(acc, hrow[s + 8 * j], orow[s + 8 * j]);
            float v = sum2(acc);
            v += __shfl_xor_sync(0xffffffffu, v, 1);
            v += __shfl_xor_sync(0xffffffffu, v, 2);
            v += __shfl_xor_sync(0xffffffffu, v, 4);
            if (s == 0) {
                int ig = ug * 2 + il, bgl = bg * 16 + b;
                float val = v + sm[OFF_OB + il];
                out[(bgl * TT + t) * II + ig] = val;
                g_inp[bgl][ig] = val;
            }
        }
        barrier(++gen);
    }
}

extern "C" void kernel_launch(void* const* d_in, const int* in_sizes, int n_in,
                              void* d_out, int out_size) {
    (void)in_sizes; (void)n_in; (void)out_size;
    cudaFuncSetAttribute(gruvae_kernel,
                         cudaFuncAttributeMaxDynamicSharedMemorySize, SMEM_BYTES);
    gruvae_kernel<<<NCTA, NTHR, SMEM_BYTES>>>(
        (const float*)d_in[0],  (const float*)d_in[1],
        (const float*)d_in[2],  (const float*)d_in[3],
        (const float*)d_in[4],  (const float*)d_in[5],
        (const float*)d_in[6],  (const float*)d_in[7],
        (const float*)d_in[8],  (const float*)d_in[9],
        (const float*)d_in[10], (const float*)d_in[11],
        (const float*)d_in[12], (const float*)d_in[13],
        (const float*)d_in[14], (const float*)d_in[15],
        (const float*)d_in[16], (const float*)d_in[17],
        (float*)d_out);
}

// round 8
// speedup vs baseline: 1.7825x; 1.2358x over previous
#include <cuda_runtime.h>
#include <math.h>

#define BB 64
#define TT 1024
#define II 64
#define HH 512
#define LL 128

#define NCTA 128
#define NTHR 256

// ---------------- smem layout (float offsets) ----------------
#define RSH 520
#define RSX 68
#define RSZ 132
#define RSO 520
#define OFF_HS 0                       /* 16 x RSH = 8320 */
#define OFF_XS 8320                    /* 2 bufs x 16 x RSX = 2176 */
#define OFF_ZS 10496                   /* 16 x RSZ = 2112 */
#define OFF_OW 12608                   /* 2 x RSO = 1040 */
#define OFF_OB 13648                   /* 16 */
#define OFF_B  13664                   /* 64 */
#define OFF_SC 13728                   /* 256*69+17 = 17681 */
/* prologue overlay: oW at 0 (64 x 514), dWih rows at 32896 (48 x 66) */
#define OFF_PDW 32896
#define SMEM_FLOATS 36100
#define SMEM_BYTES  (SMEM_FLOATS * 4)  /* 144,400 B */

typedef unsigned long long ull;

// ---------------- device scratch ----------------
__device__ float g_h[2][BB][HH];
__device__ float g_z[BB][LL];
__device__ float g_M[3 * HH * HH];     // merged decoder input-feedback weights
__device__ float g_cb[3 * HH];         // cb = dWih@ob + dbih
__device__ volatile unsigned g_flagF[NCTA * 32];      // full barrier
__device__ volatile unsigned g_flagB[4 * 32 * 32];    // per-batch-group barriers

// ---------------- math helpers ----------------
__device__ __forceinline__ void ffma2(ull& d, ull a, ull b) {
    asm("fma.rn.f32x2 %0, %1, %2, %0;" : "+l"(d) : "l"(a), "l"(b));
}
__device__ __forceinline__ ull add2(ull a, ull b) {
    ull r; asm("add.rn.f32x2 %0, %1, %2;" : "=l"(r) : "l"(a), "l"(b)); return r;
}
__device__ __forceinline__ ull dup2(float w) {
    ull r; asm("mov.b64 %0, {%1, %1};" : "=l"(r) : "f"(w)); return r;
}
__device__ __forceinline__ float sum2(ull v) {
    return __uint_as_float((unsigned)v) + __uint_as_float((unsigned)(v >> 32));
}
__device__ __forceinline__ float sigm(float x) {
    return __fdividef(1.0f, 1.0f + __expf(-x));
}
__device__ __forceinline__ float tanh_fast(float x) {
    return 1.0f - 2.0f * __fdividef(1.0f, __expf(2.0f * x) + 1.0f);
}

// ---------------- barriers (monotone flags -> graph-replay safe) ----------------
__device__ __forceinline__ void fbar(unsigned target) {
    __syncthreads();
    if (threadIdx.x == 0) { __threadfence(); g_flagF[blockIdx.x * 32] = target; }
    if (threadIdx.x < NCTA) {
        while ((int)(g_flagF[threadIdx.x * 32] - target) < 0) { }
        __threadfence();
    }
    __syncthreads();
}
__device__ __forceinline__ void gbar(int bg, int ug, unsigned target) {
    __syncthreads();
    if (threadIdx.x == 0) { __threadfence(); g_flagB[(bg * 32 + ug) * 32] = target; }
    if (threadIdx.x < 32) {
        while ((int)(g_flagB[(bg * 32 + threadIdx.x) * 32] - target) < 0) { }
        __threadfence();
    }
    __syncthreads();
}

// ---------------- staging ----------------
__device__ __forceinline__ void load_hs(float* sm, const float* hsrc, int bg) {
    for (int idx = threadIdx.x; idx < 16 * (HH / 4); idx += NTHR) {
        int b = idx >> 7, q = idx & 127;
        float4 v = reinterpret_cast<const float4*>(hsrc + (bg * 16 + b) * HH)[q];
        float* d = sm + OFF_HS + b * RSH + 4 * q;
        d[0] = v.x; d[1] = v.y; d[2] = v.z; d[3] = v.w;
    }
}
__device__ __forceinline__ void load_xs(float* xsm, const float* src, int rs, int bg) {
    for (int idx = threadIdx.x; idx < 16 * (II / 4); idx += NTHR) {
        int b = idx >> 4, q = idx & 15;
        float4 v = reinterpret_cast<const float4*>(src + (bg * 16 + b) * rs)[q];
        float* d = xsm + b * RSX + 4 * q;
        d[0] = v.x; d[1] = v.y; d[2] = v.z; d[3] = v.w;
    }
}

// 3-gate weights (+x weights) into regs, combined biases into smem
__device__ __forceinline__ void load_wregs3(
    const float* Whh, const float* Wih, const float* bih, const float* bhh,
    float* sm, int ug,
    ull (&w0)[16], ull (&w1)[16], ull (&w2)[16],
    ull (&x0)[2],  ull (&x1)[2],  ull (&x2)[2])
{
    const int tid = threadIdx.x, u = tid & 15, ks = tid >> 4;
    const int row = ug * 16 + u, k0 = ks * 32;
#pragma unroll
    for (int p = 0; p < 16; p++) {
        w0[p] = *(const ull*)(Whh + (0 * HH + row) * HH + k0 + 2 * p);
        w1[p] = *(const ull*)(Whh + (1 * HH + row) * HH + k0 + 2 * p);
        w2[p] = *(const ull*)(Whh + (2 * HH + row) * HH + k0 + 2 * p);
    }
#pragma unroll
    for (int p = 0; p < 2; p++) {
        x0[p] = *(const ull*)(Wih + (0 * HH + row) * II + ks * 4 + 2 * p);
        x1[p] = *(const ull*)(Wih + (1 * HH + row) * II + ks * 4 + 2 * p);
        x2[p] = *(const ull*)(Wih + (2 * HH + row) * II + ks * 4 + 2 * p);
    }
    if (tid < 16) {
        sm[OFF_B + tid]      = bih[ug * 16 + tid] + bhh[ug * 16 + tid];
        sm[OFF_B + 16 + tid] = bih[HH + ug * 16 + tid] + bhh[HH + ug * 16 + tid];
        sm[OFF_B + 32 + tid] = bih[2 * HH + ug * 16 + tid];
        sm[OFF_B + 48 + tid] = bhh[2 * HH + ug * 16 + tid];
    }
}

// merged 4-gate decoder weights: w0=Whh_r+M_r, w1=Whh_z+M_z, w2=Whh_n, w3=M_n
__device__ __forceinline__ void load_wregs4(
    const float* Whh, const float* bhh, float* sm, int ug,
    ull (&w0)[16], ull (&w1)[16], ull (&w2)[16], ull (&w3)[16])
{
    const int tid = threadIdx.x, u = tid & 15, ks = tid >> 4;
    const int row = ug * 16 + u, k0 = ks * 32;
#pragma unroll
    for (int p = 0; p < 16; p++) {
        w0[p] = add2(*(const ull*)(Whh + (0 * HH + row) * HH + k0 + 2 * p),
                     *(const ull*)(g_M + (0 * HH + row) * HH + k0 + 2 * p));
        w1[p] = add2(*(const ull*)(Whh + (1 * HH + row) * HH + k0 + 2 * p),
                     *(const ull*)(g_M + (1 * HH + row) * HH + k0 + 2 * p));
        w2[p] = *(const ull*)(Whh + (2 * HH + row) * HH + k0 + 2 * p);
        w3[p] = *(const ull*)(g_M + (2 * HH + row) * HH + k0 + 2 * p);
    }
    if (tid < 16) {
        sm[OFF_B + tid]      = g_cb[ug * 16 + tid] + bhh[ug * 16 + tid];
        sm[OFF_B + 16 + tid] = g_cb[HH + ug * 16 + tid] + bhh[HH + ug * 16 + tid];
        sm[OFF_B + 32 + tid] = g_cb[2 * HH + ug * 16 + tid];
        sm[OFF_B + 48 + tid] = bhh[2 * HH + ug * 16 + tid];
    }
}

// fused epilogue: all 256 threads, one per (u, b)
__device__ __forceinline__ void epilogue(float* sm, float* hout, int bg, int ug) {
    const int tid = threadIdx.x, u = tid & 15, b = tid >> 4;
    const float* s = sm + OFF_SC + tid * 69;
    float s0 = 0, s1 = 0, s2 = 0, s3 = 0;
#pragma unroll
    for (int q = 0; q < 16; q++) {
        s0 += s[q]; s1 += s[17 + q]; s2 += s[34 + q]; s3 += s[51 + q];
    }
    float r = sigm(s0 + sm[OFF_B + u]);
    float z = sigm(s1 + sm[OFF_B + 16 + u]);
    float n = tanh_fast(s3 + sm[OFF_B + 32 + u] + r * (s2 + sm[OFF_B + 48 + u]));
    float hold = sm[OFF_HS + b * RSH + ug * 16 + u];
    hout[(bg * 16 + b) * HH + ug * 16 + u] = (1.0f - z) * n + z * hold;
}

// 3-gate core (encoder + decoder t=0): h-gates r,z,nh + x-gates r,z,nx
__device__ __forceinline__ void gru_core3(
    float* sm, const float* xs, float* hout, int bg, int ug,
    ull (&w0)[16], ull (&w1)[16], ull (&w2)[16],
    ull (&x0)[2],  ull (&x1)[2],  ull (&x2)[2])
{
    const int tid = threadIdx.x, u = tid & 15, ks = tid >> 4, k0 = ks * 32;
#pragma unroll
    for (int bh = 0; bh < 2; bh++) {
        ull a0[8], a1[8], a2[8], a3[8];
#pragma unroll
        for (int j = 0; j < 8; j++) { a0[j] = a1[j] = a2[j] = a3[j] = 0ull; }
#pragma unroll
        for (int p = 0; p < 16; p++) {
            ull wa = w0[p], wb = w1[p], wc = w2[p];
#pragma unroll
            for (int j = 0; j < 8; j++) {
                ull hv = *(const ull*)(sm + OFF_HS + (bh * 8 + j) * RSH + k0 + 2 * p);
                ffma2(a0[j], hv, wa); ffma2(a1[j], hv, wb); ffma2(a2[j], hv, wc);
            }
        }
#pragma unroll
        for (int p = 0; p < 2; p++) {
            ull wa = x0[p], wb = x1[p], wc = x2[p];
#pragma unroll
            for (int j = 0; j < 8; j++) {
                ull xv = *(const ull*)(xs + (bh * 8 + j) * RSX + ks * 4 + 2 * p);
                ffma2(a0[j], xv, wa); ffma2(a1[j], xv, wb); ffma2(a3[j], xv, wc);
            }
        }
#pragma unroll
        for (int j = 0; j < 8; j++) {
            float* d = sm + OFF_SC + ((bh * 8 + j) * 16 + u) * 69 + ks;
            d[0] = sum2(a0[j]); d[17] = sum2(a1[j]);
            d[34] = sum2(a2[j]); d[51] = sum2(a3[j]);
        }
    }
    __syncthreads();
    epilogue(sm, hout, bg, ug);
}

// 4-gate merged core (decoder t>=1): r(merged), z(merged), nh(Whh), nm(M)
__device__ __forceinline__ void gru_core4(
    float* sm, float* hout, int bg, int ug,
    ull (&w0)[16], ull (&w1)[16], ull (&w2)[16], ull (&w3)[16])
{
    const int tid = threadIdx.x, u = tid & 15, ks = tid >> 4, k0 = ks * 32;
#pragma unroll
    for (int bh = 0; bh < 2; bh++) {
        ull a0[8], a1[8], a2[8], a3[8];
#pragma unroll
        for (int j = 0; j < 8; j++) { a0[j] = a1[j] = a2[j] = a3[j] = 0ull; }
#pragma unroll
        for (int p = 0; p < 16; p++) {
            ull wa = w0[p], wb = w1[p], wc = w2[p], wd = w3[p];
#pragma unroll
            for (int j = 0; j < 8; j++) {
                ull hv = *(const ull*)(sm + OFF_HS + (bh * 8 + j) * RSH + k0 + 2 * p);
                ffma2(a0[j], hv, wa); ffma2(a1[j], hv, wb);
                ffma2(a2[j], hv, wc); ffma2(a3[j], hv, wd);
            }
        }
#pragma unroll
        for (int j = 0; j < 8; j++) {
            float* d = sm + OFF_SC + ((bh * 8 + j) * 16 + u) * 69 + ks;
            d[0] = sum2(a0[j]); d[17] = sum2(a1[j]);
            d[34] = sum2(a2[j]); d[51] = sum2(a3[j]);
        }
    }
    __syncthreads();
    epilogue(sm, hout, bg, ug);
}

// out[t] = h @ oW^T + ob for this CTA's 16 batches x 2 cols (h in smem HS)
__device__ __forceinline__ void outproj(float* sm, float* out, int bg, int ug, int t) {
    const int tid = threadIdx.x;
    int s = tid & 7, il = (tid >> 3) & 1, b = tid >> 4;
    const ull* hrow = (const ull*)(sm + OFF_HS + b * RSH);
    const ull* orow = (const ull*)(sm + OFF_OW + il * RSO);
    ull acc = 0;
#pragma unroll 8
    for (int j = 0; j < 32; j++) ffma2(acc, hrow[s + 8 * j], orow[s + 8 * j]);
    float v = sum2(acc);
    v += __shfl_xor_sync(0xffffffffu, v, 1);
    v += __shfl_xor_sync(0xffffffffu, v, 2);
    v += __shfl_xor_sync(0xffffffffu, v, 4);
    if (s == 0) {
        int ig = ug * 2 + il, bgl = bg * 16 + b;
        out[(bgl * TT + t) * II + ig] = v + sm[OFF_OB + il];
    }
}

__global__ void __launch_bounds__(NTHR, 1)
gruvae_kernel(const float* __restrict__ x,    const float* __restrict__ eps,
              const float* __restrict__ eWih, const float* __restrict__ eWhh,
              const float* __restrict__ ebih, const float* __restrict__ ebhh,
              const float* __restrict__ muW,  const float* __restrict__ mub,
              const float* __restrict__ lvW,  const float* __restrict__ lvb,
              const float* __restrict__ l2hW, const float* __restrict__ l2hb,
              const float* __restrict__ dWih, const float* __restrict__ dWhh,
              const float* __restrict__ dbih, const float* __restrict__ dbhh,
              const float* __restrict__ oW,   const float* __restrict__ ob,
              float* __restrict__ out)
{
    extern __shared__ float sm[];
    const int bid = blockIdx.x, ug = bid >> 2, bg = bid & 3, tid = threadIdx.x;
    unsigned genF = g_flagF[bid * 32];
    unsigned genB = g_flagB[(bg * 32 + ug) * 32];

    ull w0[16], w1[16], w2[16], w3[16], x0[2], x1[2], x2[2];

    // ===== prologue: M = dWih @ oW (k-quarter per bg), cb = dWih@ob + dbih =====
    for (int idx = tid; idx < 64 * 128; idx += NTHR) {
        int i = idx >> 7, q = idx & 127;
        float4 v = reinterpret_cast<const float4*>(oW + i * HH)[q];
        float* d = sm + i * 514 + 4 * q;
        d[0] = v.x; d[1] = v.y; d[2] = v.z; d[3] = v.w;
    }
    for (int idx = tid; idx < 48 * 64; idx += NTHR) {
        int r = idx >> 6, i = idx & 63;
        int g = r >> 4, uu = r & 15;
        sm[OFF_PDW + r * 66 + i] = dWih[(g * HH + ug * 16 + uu) * II + i];
    }
    __syncthreads();
    {
        int kp = bg * 64 + (tid & 63);
        int rr0 = (tid >> 6) * 12;
        for (int r = rr0; r < rr0 + 12; r++) {
            const float* wrow = sm + OFF_PDW + r * 66;
            ull acc = 0ull;
#pragma unroll 8
            for (int i = 0; i < 64; i++)
                ffma2(acc, dup2(wrow[i]), *(const ull*)(sm + i * 514 + 2 * kp));
            int g = r >> 4, U = ug * 16 + (r & 15);
            *(ull*)(g_M + (g * HH + U) * HH + 2 * kp) = acc;
        }
        if (tid < 48) {
            int g = tid >> 4, uu = tid & 15, m = g * HH + ug * 16 + uu;
            const float* wrow = sm + OFF_PDW + tid * 66;
            float acc = dbih[m];
            for (int i = 0; i < 64; i++) acc += wrow[i] * ob[i];
            g_cb[m] = acc;   // identical redundant writes across bg: benign
        }
    }
    __syncthreads();

    // zero h0 slice; stage encoder weights; full barrier (covers g_M/g_cb too)
    g_h[0][bg * 16 + (tid >> 4)][ug * 16 + (tid & 15)] = 0.0f;
    load_wregs3(eWhh, eWih, ebih, ebhh, sm, ug, w0, w1, w2, x0, x1, x2);
    fbar(++genF);

    // ===== encoder (1 group-barrier per step, x double-buffered) =====
    load_xs(sm + OFF_XS, x, TT * II, bg);   // t = 0
    for (int t = 0; t < TT; t++) {
        load_hs(sm, &g_h[t & 1][0][0], bg);
        __syncthreads();
        if (t + 1 < TT)
            load_xs(sm + OFF_XS + ((t + 1) & 1) * (16 * RSX), x + (t + 1) * II, TT * II, bg);
        gru_core3(sm, sm + OFF_XS + (t & 1) * (16 * RSX), &g_h[(t + 1) & 1][0][0],
                  bg, ug, w0, w1, w2, x0, x1, x2);
        gbar(bg, ug, ++genB);
    }

    // ===== latent heads (h_n in g_h[0]) =====
    load_hs(sm, &g_h[0][0][0], bg);
    __syncthreads();
    const int RECON = BB * TT * II;
    float mu_val = 0.0f;
    if (tid < 128) {
        int b = tid & 15, j = (tid >> 4) & 3, kind = tid >> 6;
        int lat = ug * 4 + j, bglob = bg * 16 + b;
        const float4* w4 = (const float4*)((kind ? lvW : muW) + lat * HH);
        const float* hr = sm + OFF_HS + b * RSH;
        float acc = 0.0f;
#pragma unroll 4
        for (int q = 0; q < HH / 4; q++) {
            float4 w = w4[q];
            acc += hr[4*q]*w.x + hr[4*q+1]*w.y + hr[4*q+2]*w.z + hr[4*q+3]*w.w;
        }
        acc += (kind ? lvb : mub)[lat];
        out[RECON + kind * BB * LL + bglob * LL + lat] = acc;
        if (kind) sm[OFF_SC + (tid - 64)] = acc;
        mu_val = acc;
    }
    __syncthreads();
    if (tid < 64) {
        int b = tid & 15, j = tid >> 4;
        int lat = ug * 4 + j, bglob = bg * 16 + b;
        g_z[bglob][lat] = mu_val + eps[bglob * LL + lat] * expf(0.5f * sm[OFF_SC + tid]);
    }
    gbar(bg, ug, ++genB);

    // ===== h_dec = z @ l2hW^T + b -> g_h[0] =====
    {
        for (int idx = tid; idx < 16 * (LL / 4); idx += NTHR) {
            int b = idx >> 5, q = idx & 31;
            float4 v = reinterpret_cast<const float4*>(&g_z[bg * 16 + b][0])[q];
            float* d = sm + OFF_ZS + b * RSZ + 4 * q;
            d[0] = v.x; d[1] = v.y; d[2] = v.z; d[3] = v.w;
        }
        __syncthreads();
        int u = tid & 15, b = tid >> 4;
        int U = ug * 16 + u;
        const float4* w4 = (const float4*)(l2hW + U * LL);
        float a0 = 0.0f;
#pragma unroll 4
        for (int q = 0; q < LL / 4; q++) {
            float4 w = w4[q];
            const float* r0 = sm + OFF_ZS + b * RSZ + 4 * q;
            a0 += r0[0]*w.x + r0[1]*w.y + r0[2]*w.z + r0[3]*w.w;
        }
        g_h[0][bg * 16 + b][U] = a0 + l2hb[U];
    }
    // stage decoder t=0 weights, zero XS buf0, stage output rows
    load_wregs3(dWhh, dWih, dbih, dbhh, sm, ug, w0, w1, w2, x0, x1, x2);
    for (int idx = tid; idx < 16 * RSX; idx += NTHR) sm[OFF_XS + idx] = 0.0f;
    for (int idx = tid; idx < 2 * HH; idx += NTHR) {
        int i = idx >> 9, k = idx & 511;
        sm[OFF_OW + i * RSO + k] = oW[(ug * 2 + i) * HH + k];
    }
    if (tid < 2) sm[OFF_OB + tid] = ob[ug * 2 + tid];
    gbar(bg, ug, ++genB);

    // ===== decoder t = 0 (x0 = 0 -> plain GRU step) =====
    load_hs(sm, &g_h[0][0][0], bg);       // h_dec
    __syncthreads();
    gru_core3(sm, sm + OFF_XS, &g_h[1][0][0], bg, ug, w0, w1, w2, x0, x1, x2);
    gbar(bg, ug, ++genB);

    load_hs(sm, &g_h[1][0][0], bg);       // h_1
    load_wregs4(dWhh, dbhh, sm, ug, w0, w1, w2, w3);
    __syncthreads();
    outproj(sm, out, bg, ug, 0);

    // ===== decoder t = 1..1023: merged weights, 1 barrier/step =====
    for (int t = 1; t < TT; t++) {
        gru_core4(sm, &g_h[(t + 1) & 1][0][0], bg, ug, w0, w1, w2, w3);
        gbar(bg, ug, ++genB);
        load_hs(sm, &g_h[(t + 1) & 1][0][0], bg);
        __syncthreads();
        outproj(sm, out, bg, ug, t);
    }
}

extern "C" void kernel_launch(void* const* d_in, const int* in_sizes, int n_in,
                              void* d_out, int out_size) {
    (void)in_sizes; (void)n_in; (void)out_size;
    cudaFuncSetAttribute(gruvae_kernel,
                         cudaFuncAttributeMaxDynamicSharedMemorySize, SMEM_BYTES);
    gruvae_kernel<<<NCTA, NTHR, SMEM_BYTES>>>(
        (const float*)d_in[0],  (const float*)d_in[1],
        (const float*)d_in[2],  (const float*)d_in[3],
        (const float*)d_in[4],  (const float*)d_in[5],
        (const float*)d_in[6],  (const float*)d_in[7],
        (const float*)d_in[8],  (const float*)d_in[9],
        (const float*)d_in[10], (const float*)d_in[11],
        (const float*)d_in[12], (const float*)d_in[13],
        (const float*)d_in[14], (const float*)d_in[15],
        (const float*)d_in[16], (const float*)d_in[17],
        (float*)d_out);
}

// round 12
// speedup vs baseline: 2.0538x; 1.1522x over previous
#include <cuda_runtime.h>
#include <math.h>

#define BB 64
#define TT 1024
#define II 64
#define HH 512
#define LL 128
#define NCTA 128
#define NTHR 256

// ---------------- smem layout (float offsets) ----------------
// padded h rows: 16 chunks x (32 data + 8 pad) -> adjacent k-chunks in
// different banks (chunk stride 40 % 32 == 8), row stride 652 (16B aligned)
#define RSH 652
#define HSB (16*RSH)                    /* one h buffer: 10432 */
#define RSX 68
#define XSB (16*RSX)
#define RSZ 132
#define OFF_HS 0                        /* 2 x HSB = 20864 */
#define OFF_XS (2*HSB)                  /* 2 x XSB = 2176 */
#define OFF_ZS (OFF_XS + 2*XSB)        /* 23040 */
#define OFF_OW (OFF_ZS + 16*RSZ)       /* 25152: 2 x 520 */
#define OFF_OB (OFF_OW + 2*520)        /* 26192 */
#define OFF_B  (OFF_OB + 16)           /* 26208 */
#define OFF_SC (OFF_B + 64)            /* 26272 */
#define SZ_SC  (256*69 + 32)
#define OFF_PDW (OFF_SC + SZ_SC)
#define SMEM_FLOATS (OFF_PDW + 48*66 + 16)
#define SMEM_BYTES (SMEM_FLOATS*4)     /* ~189 KB */

typedef unsigned long long ull;

// ---------------- device scratch ----------------
__device__ float g_h[2][BB][HH];
__device__ float g_z[BB][LL];
__device__ float g_M[3*HH*HH];
__device__ float g_cb[3*HH];
__device__ volatile unsigned g_flagF[NCTA*32];     // full barrier flags
__device__ volatile unsigned g_flagS[4*32*32];     // per-(bg, producer-ug) step flags

// ---------------- helpers ----------------
__device__ __forceinline__ void ffma2(ull& d, ull a, ull b) {
    asm("fma.rn.f32x2 %0, %1, %2, %0;" : "+l"(d) : "l"(a), "l"(b));
}
__device__ __forceinline__ ull add2(ull a, ull b) {
    ull r; asm("add.rn.f32x2 %0, %1, %2;" : "=l"(r) : "l"(a), "l"(b)); return r;
}
__device__ __forceinline__ ull dup2(float w) {
    ull r; asm("mov.b64 %0, {%1, %1};" : "=l"(r) : "f"(w)); return r;
}
__device__ __forceinline__ float sum2(ull v) {
    return __uint_as_float((unsigned)v) + __uint_as_float((unsigned)(v >> 32));
}
__device__ __forceinline__ float sigm(float x) {
    return __fdividef(1.0f, 1.0f + __expf(-x));
}
__device__ __forceinline__ float tanh_fast(float x) {
    return 1.0f - 2.0f * __fdividef(1.0f, __expf(2.0f * x) + 1.0f);
}
__device__ __forceinline__ unsigned ld_acq(const volatile unsigned* p) {
    unsigned v;
    asm volatile("ld.acquire.gpu.global.u32 %0, [%1];" : "=r"(v) : "l"((const void*)p) : "memory");
    return v;
}
__device__ __forceinline__ void st_rel(volatile unsigned* p, unsigned v) {
    asm volatile("st.release.gpu.global.u32 [%0], %1;" :: "l"((void*)p), "r"(v) : "memory");
}

// full barrier (3 uses; monotone -> graph-replay safe)
__device__ __forceinline__ void fbar(unsigned target) {
    __syncthreads();
    if (threadIdx.x == 0) { __threadfence(); g_flagF[blockIdx.x * 32] = target; }
    if (threadIdx.x < NCTA) {
        while ((int)(g_flagF[threadIdx.x * 32] - target) < 0) { __nanosleep(64); }
        __threadfence();
    }
    __syncthreads();
}

// per-warp: wait own 4 producers, stage 16 rows x 64 cols into padded HS.
// nanosleep backoff keeps the poll from saturating L2 and delaying producers.
__device__ __forceinline__ void wait_stage(const float* __restrict__ hsrc, float* hs, int bg,
                                           unsigned target) {
    const int w = threadIdx.x >> 5, lane = threadIdx.x & 31;
    const volatile unsigned* fp = g_flagS + (bg * 32 + 4 * w + (lane & 3)) * 32;
    while (true) {
        unsigned ok = (lane < 4) ? (unsigned)((int)(ld_acq(fp) - target) >= 0) : 1u;
        if (__all_sync(0xffffffffu, ok)) break;
        __nanosleep(64);
    }
    int row = lane & 15, ch = lane >> 4;
    const float4* s4 = (const float4*)(hsrc + (bg * 16 + row) * HH + 64 * w + 32 * ch);
    float* d = hs + row * RSH + (2 * w + ch) * 40;
#pragma unroll
    for (int q = 0; q < 8; q++) *(float4*)(d + 4 * q) = s4[q];
}

// cooperative padded full-h stage (transition phases, after fbar)
__device__ __forceinline__ void load_hs_pad(float* hs, const float* hsrc, int bg) {
    for (int idx = threadIdx.x; idx < 16 * 128; idx += NTHR) {
        int row = idx >> 7, q = idx & 127;
        float4 v = reinterpret_cast<const float4*>(hsrc + (bg * 16 + row) * HH)[q];
        *(float4*)(hs + row * RSH + (q >> 3) * 40 + (q & 7) * 4) = v;
    }
}
__device__ __forceinline__ void load_xs(float* xsm, const float* src, int rs, int bg) {
    for (int idx = threadIdx.x; idx < 16 * (II / 4); idx += NTHR) {
        int b = idx >> 4, q = idx & 15;
        float4 v = reinterpret_cast<const float4*>(src + (bg * 16 + b) * rs)[q];
        *(float4*)(xsm + b * RSX + 4 * q) = v;
    }
}

// encoder-style weights into regs + biases into smem
__device__ __forceinline__ void load_wregs3(
    const float* Whh, const float* Wih, const float* bih, const float* bhh,
    float* sm, int ug,
    ull (&w0)[16], ull (&w1)[16], ull (&w2)[16],
    ull (&x0)[2],  ull (&x1)[2],  ull (&x2)[2])
{
    const int tid = threadIdx.x, u = tid & 15, ks = tid >> 4;
    const int row = ug * 16 + u, k0 = ks * 32;
#pragma unroll
    for (int p = 0; p < 16; p++) {
        w0[p] = *(const ull*)(Whh + (0 * HH + row) * HH + k0 + 2 * p);
        w1[p] = *(const ull*)(Whh + (1 * HH + row) * HH + k0 + 2 * p);
        w2[p] = *(const ull*)(Whh + (2 * HH + row) * HH + k0 + 2 * p);
    }
#pragma unroll
    for (int p = 0; p < 2; p++) {
        x0[p] = *(const ull*)(Wih + (0 * HH + row) * II + ks * 4 + 2 * p);
        x1[p] = *(const ull*)(Wih + (1 * HH + row) * II + ks * 4 + 2 * p);
        x2[p] = *(const ull*)(Wih + (2 * HH + row) * II + ks * 4 + 2 * p);
    }
    if (tid < 16) {
        sm[OFF_B + tid]      = bih[ug * 16 + tid] + bhh[ug * 16 + tid];
        sm[OFF_B + 16 + tid] = bih[HH + ug * 16 + tid] + bhh[HH + ug * 16 + tid];
        sm[OFF_B + 32 + tid] = bih[2 * HH + ug * 16 + tid];
        sm[OFF_B + 48 + tid] = bhh[2 * HH + ug * 16 + tid];
    }
}

// merged 4-gate decoder weights
__device__ __forceinline__ void load_wregs4(
    const float* Whh, const float* bhh, float* sm, int ug,
    ull (&w0)[16], ull (&w1)[16], ull (&w2)[16], ull (&w3)[16])
{
    const int tid = threadIdx.x, u = tid & 15, ks = tid >> 4;
    const int row = ug * 16 + u, k0 = ks * 32;
#pragma unroll
    for (int p = 0; p < 16; p++) {
        w0[p] = add2(*(const ull*)(Whh + (0 * HH + row) * HH + k0 + 2 * p),
                     *(const ull*)(g_M + (0 * HH + row) * HH + k0 + 2 * p));
        w1[p] = add2(*(const ull*)(Whh + (1 * HH + row) * HH + k0 + 2 * p),
                     *(const ull*)(g_M + (1 * HH + row) * HH + k0 + 2 * p));
        w2[p] = *(const ull*)(Whh + (2 * HH + row) * HH + k0 + 2 * p);
        w3[p] = *(const ull*)(g_M + (2 * HH + row) * HH + k0 + 2 * p);
    }
    if (tid < 16) {
        sm[OFF_B + tid]      = g_cb[ug * 16 + tid] + bhh[ug * 16 + tid];
        sm[OFF_B + 16 + tid] = g_cb[HH + ug * 16 + tid] + bhh[HH + ug * 16 + tid];
        sm[OFF_B + 32 + tid] = g_cb[2 * HH + ug * 16 + tid];
        sm[OFF_B + 48 + tid] = bhh[2 * HH + ug * 16 + tid];
    }
}

// GEMM + scatter (no syncs inside)
__device__ __forceinline__ void gemm3_scatter(
    const float* hs, const float* xs, float* sm,
    ull (&w0)[16], ull (&w1)[16], ull (&w2)[16],
    ull (&x0)[2],  ull (&x1)[2],  ull (&x2)[2])
{
    const int tid = threadIdx.x, u = tid & 15, ks = tid >> 4, kof = ks * 40;
#pragma unroll
    for (int bh = 0; bh < 2; bh++) {
        ull a0[8], a1[8], a2[8], a3[8];
#pragma unroll
        for (int j = 0; j < 8; j++) { a0[j] = a1[j] = a2[j] = a3[j] = 0ull; }
#pragma unroll
        for (int p = 0; p < 16; p++) {
            ull wa = w0[p], wb = w1[p], wc = w2[p];
#pragma unroll
            for (int j = 0; j < 8; j++) {
                ull hv = *(const ull*)(hs + (bh * 8 + j) * RSH + kof + 2 * p);
                ffma2(a0[j], hv, wa); ffma2(a1[j], hv, wb); ffma2(a2[j], hv, wc);
            }
        }
#pragma unroll
        for (int p = 0; p < 2; p++) {
            ull wa = x0[p], wb = x1[p], wc = x2[p];
#pragma unroll
            for (int j = 0; j < 8; j++) {
                ull xv = *(const ull*)(xs + (bh * 8 + j) * RSX + ks * 4 + 2 * p);
                ffma2(a0[j], xv, wa); ffma2(a1[j], xv, wb); ffma2(a3[j], xv, wc);
            }
        }
#pragma unroll
        for (int j = 0; j < 8; j++) {
            float* d = sm + OFF_SC + ((bh * 8 + j) * 16 + u) * 69 + ks;
            d[0] = sum2(a0[j]); d[17] = sum2(a1[j]);
            d[34] = sum2(a2[j]); d[51] = sum2(a3[j]);
        }
    }
}

__device__ __forceinline__ void gemm4_scatter(
    const float* hs, float* sm,
    ull (&w0)[16], ull (&w1)[16], ull (&w2)[16], ull (&w3)[16])
{
    const int tid = threadIdx.x, u = tid & 15, ks = tid >> 4, kof = ks * 40;
#pragma unroll
    for (int bh = 0; bh < 2; bh++) {
        ull a0[8], a1[8], a2[8], a3[8];
#pragma unroll
        for (int j = 0; j < 8; j++) { a0[j] = a1[j] = a2[j] = a3[j] = 0ull; }
#pragma unroll
        for (int p = 0; p < 16; p++) {
            ull wa = w0[p], wb = w1[p], wc = w2[p], wd = w3[p];
#pragma unroll
            for (int j = 0; j < 8; j++) {
                ull hv = *(const ull*)(hs + (bh * 8 + j) * RSH + kof + 2 * p);
                ffma2(a0[j], hv, wa); ffma2(a1[j], hv, wb);
                ffma2(a2[j], hv, wc); ffma2(a3[j], hv, wd);
            }
        }
#pragma unroll
        for (int j = 0; j < 8; j++) {
            float* d = sm + OFF_SC + ((bh * 8 + j) * 16 + u) * 69 + ks;
            d[0] = sum2(a0[j]); d[17] = sum2(a1[j]);
            d[34] = sum2(a2[j]); d[51] = sum2(a3[j]);
        }
    }
}

// reduce + activations + own-slice STG (hold read from padded hs)
__device__ __forceinline__ void epilogue(float* sm, const float* hs, float* gdst,
                                         int bg, int ug) {
    const int tid = threadIdx.x, u = tid & 15, b = tid >> 4;
    const float* s = sm + OFF_SC + tid * 69;
    float s0 = 0, s1 = 0, s2 = 0, s3 = 0;
#pragma unroll
    for (int q = 0; q < 16; q++) {
        s0 += s[q]; s1 += s[17 + q]; s2 += s[34 + q]; s3 += s[51 + q];
    }
    float r = sigm(s0 + sm[OFF_B + u]);
    float z = sigm(s1 + sm[OFF_B + 16 + u]);
    float n = tanh_fast(s3 + sm[OFF_B + 32 + u] + r * (s2 + sm[OFF_B + 48 + u]));
    const int U = ug * 16 + u;
    float hold = hs[b * RSH + (U >> 5) * 40 + (U & 31)];
    gdst[(bg * 16 + b) * HH + U] = (1.0f - z) * n + z * hold;
}

// out[t] slice (2 cols x 16 batches) from padded hs
__device__ __forceinline__ void outproj(const float* sm, const float* hs,
                                        float* out, int bg, int ug, int t) {
    const int tid = threadIdx.x;
    int s = tid & 7, il = (tid >> 3) & 1, b = tid >> 4;
    const ull* hrow = (const ull*)(hs + b * RSH);
    const ull* orow = (const ull*)(sm + OFF_OW + il * 520);
    ull acc = 0;
#pragma unroll
    for (int c = 0; c < 16; c++) {
        ffma2(acc, hrow[c * 20 + s],     orow[c * 16 + s]);
        ffma2(acc, hrow[c * 20 + 8 + s], orow[c * 16 + 8 + s]);
    }
    float v = sum2(acc);
    v += __shfl_xor_sync(0xffffffffu, v, 1);
    v += __shfl_xor_sync(0xffffffffu, v, 2);
    v += __shfl_xor_sync(0xffffffffu, v, 4);
    if (s == 0) {
        int ig = ug * 2 + il, bgl = bg * 16 + b;
        out[(bgl * TT + t) * II + ig] = v + sm[OFF_OB + il];
    }
}

__global__ void __launch_bounds__(NTHR, 1)
gruvae_kernel(const float* __restrict__ x,    const float* __restrict__ eps,
              const float* __restrict__ eWih, const float* __restrict__ eWhh,
              const float* __restrict__ ebih, const float* __restrict__ ebhh,
              const float* __restrict__ muW,  const float* __restrict__ mub,
              const float* __restrict__ lvW,  const float* __restrict__ lvb,
              const float* __restrict__ l2hW, const float* __restrict__ l2hb,
              const float* __restrict__ dWih, const float* __restrict__ dWhh,
              const float* __restrict__ dbih, const float* __restrict__ dbhh,
              const float* __restrict__ oW,   const float* __restrict__ ob,
              float* __restrict__ out)
{
    extern __shared__ float sm[];
    const int bid = blockIdx.x, ug = bid >> 2, bg = bid & 3, tid = threadIdx.x;
    unsigned gF = g_flagF[bid * 32];
    const unsigned sbase = g_flagS[(bg * 32 + ug) * 32];
    volatile unsigned* myflag = g_flagS + (bg * 32 + ug) * 32;

    ull w0[16], w1[16], w2[16], w3[16], x0[2], x1[2], x2[2];

    // ===== prologue: M = dWih @ oW (k-quarter per bg), cb = dWih@ob + dbih =====
    // oW staged at stride 514 (scalar stores: 514 % 4 != 0, float4 would trap)
    for (int idx = tid; idx < 64 * 512; idx += NTHR) {
        int i = idx >> 9, k = idx & 511;
        sm[i * 514 + k] = oW[i * HH + k];
    }
    for (int idx = tid; idx < 48 * 64; idx += NTHR) {
        int r = idx >> 6, i = idx & 63;
        sm[OFF_PDW + r * 66 + i] = dWih[((r >> 4) * HH + ug * 16 + (r & 15)) * II + i];
    }
    __syncthreads();
    {
        int kp = bg * 64 + (tid & 63);
        int rr0 = (tid >> 6) * 12;
        for (int r = rr0; r < rr0 + 12; r++) {
            const float* wrow = sm + OFF_PDW + r * 66;
            ull acc = 0ull;
#pragma unroll 8
            for (int i = 0; i < 64; i++)
                ffma2(acc, dup2(wrow[i]), *(const ull*)(sm + i * 514 + 2 * kp));
            int g = r >> 4, U = ug * 16 + (r & 15);
            *(ull*)(g_M + (g * HH + U) * HH + 2 * kp) = acc;
        }
        if (tid < 48) {
            int g = tid >> 4, m = g * HH + ug * 16 + (tid & 15);
            const float* wrow = sm + OFF_PDW + tid * 66;
            float acc = dbih[m];
            for (int i = 0; i < 64; i++) acc += wrow[i] * ob[i];
            g_cb[m] = acc;
        }
    }
    __syncthreads();

    // zero own h0 slice; mark h_0 produced; stage x[0]; encoder weights
    g_h[0][bg * 16 + (tid >> 4)][ug * 16 + (tid & 15)] = 0.0f;
    if (tid == 0) *myflag = sbase + 1;
    load_xs(sm + OFF_XS, x, TT * II, bg);
    load_wregs3(eWhh, eWih, ebih, ebhh, sm, ug, w0, w1, w2, x0, x1, x2);
    fbar(++gF);

    // ===== encoder: dataflow, no group barrier =====
    for (int t = 0; t < TT; t++) {
        const int par = t & 1;
        float* hsb = sm + OFF_HS + par * HSB;
        wait_stage(&g_h[par][0][0], hsb, bg, sbase + 1 + t);
        gemm3_scatter(hsb, sm + OFF_XS + par * XSB, sm, w0, w1, w2, x0, x1, x2);
        if (t + 1 < TT)
            load_xs(sm + OFF_XS + ((t + 1) & 1) * XSB, x + (t + 1) * II, TT * II, bg);
        __syncthreads();
        epilogue(sm, hsb, &g_h[1 - par][0][0], bg, ug);
        __syncthreads();
        if (tid == 0) st_rel(myflag, sbase + 2 + t);
    }

    // ===== latent heads (h_1024 in g_h[0]) =====
    fbar(++gF);
    load_hs_pad(sm + OFF_HS, &g_h[0][0][0], bg);
    __syncthreads();
    const int RECON = BB * TT * II;
    float mu_val = 0.0f;
    if (tid < 128) {
        int b = tid & 15, j = (tid >> 4) & 3, kind = tid >> 6;
        int lat = ug * 4 + j, bglob = bg * 16 + b;
        const float4* w4 = (const float4*)((kind ? lvW : muW) + lat * HH);
        const float* hr = sm + OFF_HS + b * RSH;
        float acc = 0.0f;
#pragma unroll
        for (int c = 0; c < 16; c++) {
            const float4* h4 = (const float4*)(hr + c * 40);
#pragma unroll
            for (int qq = 0; qq < 8; qq++) {
                float4 w = w4[c * 8 + qq], h = h4[qq];
                acc += h.x * w.x + h.y * w.y + h.z * w.z + h.w * w.w;
            }
        }
        acc += (kind ? lvb : mub)[lat];
        out[RECON + kind * BB * LL + bglob * LL + lat] = acc;
        if (kind) sm[OFF_SC + (tid - 64)] = acc;
        mu_val = acc;
    }
    __syncthreads();
    if (tid < 64) {
        int b = tid & 15, j = tid >> 4;
        int lat = ug * 4 + j, bglob = bg * 16 + b;
        g_z[bglob][lat] = mu_val + eps[bglob * LL + lat] * expf(0.5f * sm[OFF_SC + tid]);
    }
    fbar(++gF);

    // ===== h_dec -> g_h[1]; stage decoder t=0 state =====
    {
        for (int idx = tid; idx < 16 * (LL / 4); idx += NTHR) {
            int b = idx >> 5, q = idx & 31;
            float4 v = reinterpret_cast<const float4*>(&g_z[bg * 16 + b][0])[q];
            *(float4*)(sm + OFF_ZS + b * RSZ + 4 * q) = v;
        }
        __syncthreads();
        int u = tid & 15, b = tid >> 4;
        int U = ug * 16 + u;
        const float4* w4 = (const float4*)(l2hW + U * LL);
        float a0 = 0.0f;
#pragma unroll 4
        for (int q = 0; q < LL / 4; q++) {
            float4 w = w4[q];
            const float* r0 = sm + OFF_ZS + b * RSZ + 4 * q;
            a0 += r0[0]*w.x + r0[1]*w.y + r0[2]*w.z + r0[3]*w.w;
        }
        g_h[1][bg * 16 + b][U] = a0 + l2hb[U];
    }
    load_wregs3(dWhh, dWih, dbih, dbhh, sm, ug, w0, w1, w2, x0, x1, x2);
    for (int idx = tid; idx < XSB; idx += NTHR) sm[OFF_XS + idx] = 0.0f;  // x_0 = 0
    for (int idx = tid; idx < 2 * HH; idx += NTHR)
        sm[OFF_OW + (idx >> 9) * 520 + (idx & 511)] = oW[(ug * 2 + (idx >> 9)) * HH + (idx & 511)];
    if (tid < 2) sm[OFF_OB + tid] = ob[ug * 2 + tid];
    __syncthreads();
    if (tid == 0) st_rel(myflag, sbase + 1026);

    // ===== decoder t=0 (plain 3-gate, x=0); h_dec in g_h[1] =====
    {
        float* hsb = sm + OFF_HS + 1 * HSB;
        wait_stage(&g_h[1][0][0], hsb, bg, sbase + 1026);
        gemm3_scatter(hsb, sm + OFF_XS, sm, w0, w1, w2, x0, x1, x2);
        __syncthreads();
        epilogue(sm, hsb, &g_h[0][0][0], bg, ug);     // h_1 -> g_h[0]
        __syncthreads();
        if (tid == 0) st_rel(myflag, sbase + 1027);
    }
    load_wregs4(dWhh, dbhh, sm, ug, w0, w1, w2, w3);

    // ===== decoder t=1..1023: merged weights, dataflow, lagged outproj =====
    for (int t = 1; t < TT; t++) {
        const int par = (t + 1) & 1;                   // h_t lives in g_h[par]
        float* hsb = sm + OFF_HS + par * HSB;
        wait_stage(&g_h[par][0][0], hsb, bg, sbase + 1026 + t);
        gemm4_scatter(hsb, sm, w0, w1, w2, w3);
        __syncthreads();
        epilogue(sm, hsb, &g_h[1 - par][0][0], bg, ug); // h_{t+1} -> g_h[1-par]
        __syncthreads();
        if (tid == 0) st_rel(myflag, sbase + 1027 + t);
        outproj(sm, hsb, out, bg, ug, t - 1);           // out[t-1] from h_t
    }

    // ===== tail: out[1023] from h_1024 (in g_h[1]) =====
    {
        float* hsb = sm + OFF_HS + 1 * HSB;
        wait_stage(&g_h[1][0][0], hsb, bg, sbase + 2050);
        __syncthreads();
        outproj(sm, hsb, out, bg, ug, TT - 1);
    }
}

extern "C" void kernel_launch(void* const* d_in, const int* in_sizes, int n_in,
                              void* d_out, int out_size) {
    (void)in_sizes; (void)n_in; (void)out_size;
    cudaFuncSetAttribute(gruvae_kernel,
                         cudaFuncAttributeMaxDynamicSharedMemorySize, SMEM_BYTES);
    gruvae_kernel<<<NCTA, NTHR, SMEM_BYTES>>>(
        (const float*)d_in[0],  (const float*)d_in[1],
        (const float*)d_in[2],  (const float*)d_in[3],
        (const float*)d_in[4],  (const float*)d_in[5],
        (const float*)d_in[6],  (const float*)d_in[7],
        (const float*)d_in[8],  (const float*)d_in[9],
        (const float*)d_in[10], (const float*)d_in[11],
        (const float*)d_in[12], (const float*)d_in[13],
        (const float*)d_in[14], (const float*)d_in[15],
        (const float*)d_in[16], (const float*)d_in[17],
        (float*)d_out);
}